// round 3
// baseline (speedup 1.0000x reference)
#include <cuda_runtime.h>

#define BB 4
#define CC 256
#define HH 56
#define WW 56
#define HW 3136          // 56*56
#define CK 2304          // C*9
#define COT 128          // co tile
#define PXT 64           // pixel tile (3136 = 49*64 exactly)

// ---------------- scratch (static device memory; no allocations) ----------------
__device__ float g_off[BB*18*HW];      // offset conv output
__device__ float g_t1 [BB*CC*HW];      // deform conv output (pre-BN)
__device__ float g_t3 [BB*CC*HW];      // conv2 output (pre-BN)
__device__ float g_w1t[CK*CC];         // w1 transposed: [c*9+k][co]
__device__ float g_w2t[CK*CC];         // w2 transposed
__device__ float g_s1[CC], g_h1[CC];   // bn1 scale/shift
__device__ float g_s2[CC], g_h2[CC];   // bn2 scale/shift

// ---------------- weight transpose: [co][c][k] -> [c*9+k][co] ----------------
__global__ void prep_w(const float* __restrict__ w1, const float* __restrict__ w2) {
    int i = blockIdx.x * blockDim.x + threadIdx.x;
    if (i < CK*CC) {
        int co = i / CK, r = i % CK;
        g_w1t[r*CC + co] = w1[i];
        g_w2t[r*CC + co] = w2[i];
    }
}

__global__ void zero_off() {
    int i = blockIdx.x * blockDim.x + threadIdx.x;
    if (i < BB*18*HW) g_off[i] = 0.f;
}

// ---------------- offset conv: 3x3, dil=2, pad=2, C=256 -> 18 ----------------
// grid (14, 2, B), 224 threads. Each block: 224 pixels (4 rows), one C-half.
// Two partial sums per output combined via atomicAdd (fp add is commutative ->
// bitwise deterministic with exactly 2 contributors on a zeroed buffer).
__global__ void __launch_bounds__(224) offset_conv(const float* __restrict__ x,
                                                   const float* __restrict__ w_off) {
    int b = blockIdx.z, chalf = blockIdx.y;
    int p = blockIdx.x * 224 + threadIdx.x;
    int h = p / WW, w = p % WW;
    __shared__ float w_sm[162];
    float acc[18];
#pragma unroll
    for (int co = 0; co < 18; co++) acc[co] = 0.f;

    const float* xb = x + ((size_t)(b*CC + chalf*128)) * HW;
    for (int c = 0; c < 128; c++) {
        __syncthreads();
        if (threadIdx.x < 162) {
            int co = threadIdx.x / 9, kk = threadIdx.x % 9;
            w_sm[threadIdx.x] = w_off[co*CK + (chalf*128 + c)*9 + kk];
        }
        __syncthreads();
        float sv[9];
        const float* xp = xb + c*HW;
#pragma unroll
        for (int k = 0; k < 9; k++) {
            int yy = h + (k/3)*2 - 2;
            int xx = w + (k%3)*2 - 2;
            sv[k] = ((unsigned)yy < HH && (unsigned)xx < WW) ? xp[yy*WW + xx] : 0.f;
        }
#pragma unroll
        for (int co = 0; co < 18; co++) {
            float a = acc[co];
#pragma unroll
            for (int k = 0; k < 9; k++) a = fmaf(sv[k], w_sm[co*9 + k], a);
            acc[co] = a;
        }
    }
#pragma unroll
    for (int co = 0; co < 18; co++)
        atomicAdd(&g_off[(b*18 + co)*HW + p], acc[co]);
}

// ---------------- deformable conv: implicit GEMM 128co x 64px ----------------
// grid (49, 2, B), 256 threads. Thread tile 8co x 4px.
__global__ void __launch_bounds__(256) deform_conv(const float* __restrict__ x,
                                                   const float* __restrict__ b_off) {
    int b   = blockIdx.z;
    int cob = blockIdx.y * COT;
    int pb  = blockIdx.x * PXT;
    int tid = threadIdx.x;

    __shared__ float s_w[9][COT];
    __shared__ float s_v[9][PXT];
    __shared__ int   s_y0[9*PXT];
    __shared__ int   s_x0[9*PXT];
    __shared__ float s_wy[9*PXT];
    __shared__ float s_wx[9*PXT];

    // sampling metadata (per k, per pixel) — computed once per block
    for (int i = tid; i < 9*PXT; i += 256) {
        int k = i / PXT, j = i % PXT;
        int p = pb + j;
        int h = p / WW, w = p % WW;
        float dy = g_off[(b*18 + 2*k    )*HW + p] + b_off[2*k];
        float dx = g_off[(b*18 + 2*k + 1)*HW + p] + b_off[2*k + 1];
        float py = (float)(h + (k/3)*2 - 2) + dy;
        float px = (float)(w + (k%3)*2 - 2) + dx;
        float y0f = floorf(py), x0f = floorf(px);
        s_y0[i] = (int)y0f;  s_x0[i] = (int)x0f;
        s_wy[i] = py - y0f;  s_wx[i] = px - x0f;
    }
    __syncthreads();

    float acc[8][4];
#pragma unroll
    for (int i = 0; i < 8; i++)
#pragma unroll
        for (int j = 0; j < 4; j++) acc[i][j] = 0.f;

    int tco = (tid / 16) * 8;   // 0..120
    int tpx = (tid % 16) * 4;   // 0..60

    for (int c = 0; c < CC; c++) {
        // stage weights [k][co], coalesced from transposed layout
        for (int i = tid; i < 9*COT; i += 256) {
            int k = i / COT, co = i % COT;
            s_w[k][co] = g_w1t[(c*9 + k)*CC + cob + co];
        }
        // bilinear-sampled operand [k][px]
        const float* xp = x + ((size_t)(b*CC + c)) * HW;
        for (int i = tid; i < 9*PXT; i += 256) {
            int y0 = s_y0[i], x0 = s_x0[i];
            float wy = s_wy[i], wx = s_wx[i];
            float v00 = ((unsigned)y0     < HH && (unsigned)x0     < WW) ? xp[y0*WW + x0]         : 0.f;
            float v01 = ((unsigned)y0     < HH && (unsigned)(x0+1) < WW) ? xp[y0*WW + x0 + 1]     : 0.f;
            float v10 = ((unsigned)(y0+1) < HH && (unsigned)x0     < WW) ? xp[(y0+1)*WW + x0]     : 0.f;
            float v11 = ((unsigned)(y0+1) < HH && (unsigned)(x0+1) < WW) ? xp[(y0+1)*WW + x0 + 1] : 0.f;
            s_v[i/PXT][i%PXT] = v00*(1.f-wy)*(1.f-wx) + v01*(1.f-wy)*wx
                              + v10*wy*(1.f-wx)       + v11*wy*wx;
        }
        __syncthreads();
#pragma unroll
        for (int k = 0; k < 9; k++) {
            float a0[8], b0[4];
            *(float4*)&a0[0] = *(const float4*)&s_w[k][tco];
            *(float4*)&a0[4] = *(const float4*)&s_w[k][tco + 4];
            *(float4*)&b0[0] = *(const float4*)&s_v[k][tpx];
#pragma unroll
            for (int i = 0; i < 8; i++)
#pragma unroll
                for (int j = 0; j < 4; j++)
                    acc[i][j] = fmaf(a0[i], b0[j], acc[i][j]);
        }
        __syncthreads();
    }

#pragma unroll
    for (int i = 0; i < 8; i++) {
        float* op = g_t1 + ((size_t)(b*CC + cob + tco + i)) * HW + pb + tpx;
#pragma unroll
        for (int j = 0; j < 4; j++) op[j] = acc[i][j];
    }
}

// ---------------- BN stats: per-channel mean/var -> scale/shift ----------------
// which==0: stats of g_t1 -> g_s1/g_h1 ;  which==1: stats of g_t3 -> g_s2/g_h2
__global__ void bn_stats(int which, const float* __restrict__ gamma,
                         const float* __restrict__ beta) {
    int c = blockIdx.x;
    const float* t = (which == 0) ? g_t1 : g_t3;
    float s = 0.f, q = 0.f;
    for (int b = 0; b < BB; b++) {
        const float* p = t + ((size_t)(b*CC + c)) * HW;
        for (int i = threadIdx.x; i < HW; i += 256) {
            float v = p[i];
            s += v; q += v*v;
        }
    }
    __shared__ float rs[8], rq[8];
#pragma unroll
    for (int o = 16; o; o >>= 1) {
        s += __shfl_down_sync(0xffffffffu, s, o);
        q += __shfl_down_sync(0xffffffffu, q, o);
    }
    int wid = threadIdx.x / 32, lid = threadIdx.x % 32;
    if (lid == 0) { rs[wid] = s; rq[wid] = q; }
    __syncthreads();
    if (threadIdx.x == 0) {
        s = rs[0]; q = rq[0];
        for (int i = 1; i < 8; i++) { s += rs[i]; q += rq[i]; }
        float n = (float)(BB*HW);
        float mean = s / n;
        float var  = q / n - mean*mean;
        float scale = gamma[c] * rsqrtf(var + 1e-5f);
        if (which == 0) { g_s1[c] = scale; g_h1[c] = beta[c] - mean*scale; }
        else            { g_s2[c] = scale; g_h2[c] = beta[c] - mean*scale; }
    }
}

// ---------------- conv2: 3x3 pad=1, fused BN1+ReLU on operand load ----------------
__global__ void __launch_bounds__(256) conv2_k() {
    int b   = blockIdx.z;
    int cob = blockIdx.y * COT;
    int pb  = blockIdx.x * PXT;
    int tid = threadIdx.x;

    __shared__ float s_w[9][COT];
    __shared__ float s_v[9][PXT];

    float acc[8][4];
#pragma unroll
    for (int i = 0; i < 8; i++)
#pragma unroll
        for (int j = 0; j < 4; j++) acc[i][j] = 0.f;

    int tco = (tid / 16) * 8;
    int tpx = (tid % 16) * 4;

    for (int c = 0; c < CC; c++) {
        for (int i = tid; i < 9*COT; i += 256) {
            int k = i / COT, co = i % COT;
            s_w[k][co] = g_w2t[(c*9 + k)*CC + cob + co];
        }
        float sc = g_s1[c], sh = g_h1[c];
        const float* tp = g_t1 + ((size_t)(b*CC + c)) * HW;
        for (int i = tid; i < 9*PXT; i += 256) {
            int k = i / PXT, j = i % PXT;
            int p = pb + j;
            int h = p / WW, w = p % WW;
            int y = h + k/3 - 1, xx = w + k%3 - 1;
            float v = 0.f;
            if ((unsigned)y < HH && (unsigned)xx < WW)
                v = fmaxf(fmaf(tp[y*WW + xx], sc, sh), 0.f);
            s_v[k][j] = v;
        }
        __syncthreads();
#pragma unroll
        for (int k = 0; k < 9; k++) {
            float a0[8], b0[4];
            *(float4*)&a0[0] = *(const float4*)&s_w[k][tco];
            *(float4*)&a0[4] = *(const float4*)&s_w[k][tco + 4];
            *(float4*)&b0[0] = *(const float4*)&s_v[k][tpx];
#pragma unroll
            for (int i = 0; i < 8; i++)
#pragma unroll
                for (int j = 0; j < 4; j++)
                    acc[i][j] = fmaf(a0[i], b0[j], acc[i][j]);
        }
        __syncthreads();
    }

#pragma unroll
    for (int i = 0; i < 8; i++) {
        float* op = g_t3 + ((size_t)(b*CC + cob + tco + i)) * HW + pb + tpx;
#pragma unroll
        for (int j = 0; j < 4; j++) op[j] = acc[i][j];
    }
}

// ---------------- epilogue: out = relu(bn2(t3) + x), float4 ----------------
__global__ void epilogue(const float* __restrict__ x, float* __restrict__ out) {
    int i4 = blockIdx.x * blockDim.x + threadIdx.x;
    if (i4 < BB*CC*HW/4) {
        int i = i4 * 4;
        int c = (i / HW) % CC;              // HW divisible by 4: all 4 lanes same channel
        float sc = g_s2[c], sh = g_h2[c];
        float4 t  = *(const float4*)&g_t3[i];
        float4 xv = *(const float4*)&x[i];
        float4 o;
        o.x = fmaxf(fmaf(t.x, sc, sh) + xv.x, 0.f);
        o.y = fmaxf(fmaf(t.y, sc, sh) + xv.y, 0.f);
        o.z = fmaxf(fmaf(t.z, sc, sh) + xv.z, 0.f);
        o.w = fmaxf(fmaf(t.w, sc, sh) + xv.w, 0.f);
        *(float4*)&out[i] = o;
    }
}

// ---------------- launch ----------------
extern "C" void kernel_launch(void* const* d_in, const int* in_sizes, int n_in,
                              void* d_out, int out_size) {
    const float* x      = (const float*)d_in[0];
    const float* w_off  = (const float*)d_in[1];
    const float* b_off  = (const float*)d_in[2];
    const float* w1     = (const float*)d_in[3];
    const float* gamma1 = (const float*)d_in[4];
    const float* beta1  = (const float*)d_in[5];
    const float* w2     = (const float*)d_in[6];
    const float* gamma2 = (const float*)d_in[7];
    const float* beta2  = (const float*)d_in[8];
    float* out = (float*)d_out;

    prep_w<<<(CK*CC + 255)/256, 256>>>(w1, w2);
    zero_off<<<(BB*18*HW + 255)/256, 256>>>();
    offset_conv<<<dim3(14, 2, BB), 224>>>(x, w_off);
    deform_conv<<<dim3(49, 2, BB), 256>>>(x, b_off);
    bn_stats<<<CC, 256>>>(0, gamma1, beta1);
    conv2_k<<<dim3(49, 2, BB), 256>>>();
    bn_stats<<<CC, 256>>>(1, gamma2, beta2);
    epilogue<<<(BB*CC*HW/4 + 255)/256, 256>>>(x, out);
}

// round 5
// speedup vs baseline: 1.5752x; 1.5752x over previous
#include <cuda_runtime.h>

#define BB 4
#define CC 256
#define HH 56
#define WW 56
#define HW 3136          // 56*56
#define CK 2304          // C*9
#define COT 128          // co tile
#define PXT 64           // pixel tile (3136 = 49*64)
#define NS  (9*PXT)      // 576 samples per block per channel

typedef unsigned long long u64;

// ---------------- packed fp32x2 helpers ----------------
__device__ __forceinline__ u64 dup2(float x) {
    unsigned u = __float_as_uint(x);
    u64 r; asm("mov.b64 %0, {%1, %1};" : "=l"(r) : "r"(u)); return r;
}
__device__ __forceinline__ void fma2(u64& d, u64 a, u64 b) {
    asm("fma.rn.f32x2 %0, %1, %2, %0;" : "+l"(d) : "l"(a), "l"(b));
}
__device__ __forceinline__ void unpack2(u64 v, float& lo, float& hi) {
    unsigned a, b;
    asm("mov.b64 {%0, %1}, %2;" : "=r"(a), "=r"(b) : "l"(v));
    lo = __uint_as_float(a); hi = __uint_as_float(b);
}
// ---------------- cp.async helpers ----------------
__device__ __forceinline__ void cp16(unsigned dst, const void* src) {
    asm volatile("cp.async.ca.shared.global [%0], [%1], 16;" :: "r"(dst), "l"(src));
}
__device__ __forceinline__ void cp_commit() { asm volatile("cp.async.commit_group;"); }
__device__ __forceinline__ void cp_wait0()  { asm volatile("cp.async.wait_group 0;"); }

// ---------------- scratch (static device memory) ----------------
__device__ float g_offp[4][BB*18*HW];  // offset conv partials (C-quarters)
__device__ float g_t1 [BB*CC*HW];      // deform conv output (pre-BN)
__device__ float g_t3 [BB*CC*HW];      // conv2 output (pre-BN)
__device__ float g_w1t[CK*CC];         // w1 transposed: [c*9+k][co]
__device__ float g_w2t[CK*CC];         // w2 transposed
__device__ float g_s1[CC], g_h1[CC];   // bn1 scale/shift
__device__ float g_s2[CC], g_h2[CC];   // bn2 scale/shift

// ---------------- weight transpose: [co][c][k] -> [c*9+k][co] ----------------
__global__ void prep_w(const float* __restrict__ w1, const float* __restrict__ w2) {
    int i = blockIdx.x * blockDim.x + threadIdx.x;
    if (i < CK*CC) {
        int co = i / CK, r = i % CK;
        g_w1t[r*CC + co] = w1[i];
        g_w2t[r*CC + co] = w2[i];
    }
}

// ---------------- offset conv: 3x3 dil=2 pad=2, C-quarter partials, f32x2 ----------------
// grid (14, 4, B), 224 threads. Each block: 224 pixels, 64 channels. No atomics:
// partials summed deterministically in deform_conv's meta phase.
__global__ void __launch_bounds__(224) offset_conv(const float* __restrict__ x,
                                                   const float* __restrict__ w_off) {
    int b = blockIdx.z, q = blockIdx.y;
    int p = blockIdx.x * 224 + threadIdx.x;
    int h = p / WW, w = p % WW;
    __shared__ float w_sm[9][20];   // [k][co] padded (18 -> 20), 8B-aligned rows
    u64 acc[9];
#pragma unroll
    for (int m = 0; m < 9; m++) acc[m] = 0ull;

    const float* xb = x + ((size_t)(b*CC + q*64)) * HW;
    for (int c = 0; c < 64; c++) {
        __syncthreads();
        if (threadIdx.x < 162) {
            int co = threadIdx.x / 9, kk = threadIdx.x % 9;
            w_sm[kk][co] = w_off[co*CK + (q*64 + c)*9 + kk];
        }
        __syncthreads();
        float sv[9];
        const float* xp = xb + c*HW;
#pragma unroll
        for (int k = 0; k < 9; k++) {
            int yy = h + (k/3)*2 - 2;
            int xx = w + (k%3)*2 - 2;
            sv[k] = ((unsigned)yy < HH && (unsigned)xx < WW) ? xp[yy*WW + xx] : 0.f;
        }
#pragma unroll
        for (int k = 0; k < 9; k++) {
            u64 s2 = dup2(sv[k]);
            const u64* wp = (const u64*)&w_sm[k][0];
#pragma unroll
            for (int m = 0; m < 9; m++) fma2(acc[m], wp[m], s2);
        }
    }
#pragma unroll
    for (int m = 0; m < 9; m++) {
        float lo, hi; unpack2(acc[m], lo, hi);
        g_offp[q][(size_t)(b*18 + 2*m    )*HW + p] = lo;
        g_offp[q][(size_t)(b*18 + 2*m + 1)*HW + p] = hi;
    }
}

// ---------------- deformable conv: pipelined implicit GEMM, f32x2 ----------------
// grid (49, 2, B), 256 threads. Thread tile 8co x 4px (acc packed as co-pairs).
__global__ void __launch_bounds__(256, 2) deform_conv(const float* __restrict__ x,
                                                      const float* __restrict__ b_off) {
    int b   = blockIdx.z;
    int cob = blockIdx.y * COT;
    int pb  = blockIdx.x * PXT;
    int tid = threadIdx.x;

    __shared__ float s_w[2][9][COT];   // double-buffered weights
    __shared__ float s_v[2][NS];       // double-buffered sampled operand
    __shared__ int   s_ix[4][NS];      // 4 clamped corner flat indices
    __shared__ float s_bw[4][NS];      // 4 masked bilinear weights

    // ---- meta (once per block) ----
    for (int i = tid; i < NS; i += 256) {
        int k = i / PXT, j = i % PXT;
        int p = pb + j, h = p / WW, w = p % WW;
        size_t o = (size_t)(b*18 + 2*k)*HW + p;
        float dy = g_offp[0][o] + g_offp[1][o] + g_offp[2][o] + g_offp[3][o] + b_off[2*k];
        o += HW;
        float dx = g_offp[0][o] + g_offp[1][o] + g_offp[2][o] + g_offp[3][o] + b_off[2*k + 1];
        float py = (float)(h + (k/3)*2 - 2) + dy;
        float px = (float)(w + (k%3)*2 - 2) + dx;
        float y0f = floorf(py), x0f = floorf(px);
        float wy = py - y0f, wx = px - x0f;
        int yi = (int)y0f, xi = (int)x0f;
        float vy0 = ((unsigned)yi      < HH) ? 1.f : 0.f;
        float vy1 = ((unsigned)(yi+1)  < HH) ? 1.f : 0.f;
        float vx0 = ((unsigned)xi      < WW) ? 1.f : 0.f;
        float vx1 = ((unsigned)(xi+1)  < WW) ? 1.f : 0.f;
        int cy0 = min(max(yi,   0), HH-1), cy1 = min(max(yi+1, 0), HH-1);
        int cx0 = min(max(xi,   0), WW-1), cx1 = min(max(xi+1, 0), WW-1);
        s_ix[0][i] = cy0*WW + cx0;  s_ix[1][i] = cy0*WW + cx1;
        s_ix[2][i] = cy1*WW + cx0;  s_ix[3][i] = cy1*WW + cx1;
        s_bw[0][i] = (1.f-wy)*(1.f-wx)*vy0*vx0;
        s_bw[1][i] = (1.f-wy)*wx      *vy0*vx1;
        s_bw[2][i] = wy*(1.f-wx)      *vy1*vx0;
        s_bw[3][i] = wy*wx            *vy1*vx1;
    }
    __syncthreads();

    const float* xb = x + (size_t)b*CC*HW;
    float pv[3][4];

    // weight staging for channel c into buffer dbuf (288 x 16B via cp.async)
    auto stage_w = [&](int c, int dbuf) {
        unsigned base = (unsigned)__cvta_generic_to_shared(&s_w[dbuf][0][0]);
        {
            int m = tid, k = m >> 5, off = (m & 31) * 4;
            cp16(base + (unsigned)(k*COT + off)*4u, g_w1t + (size_t)(c*9 + k)*CC + cob + off);
        }
        if (tid < 32) {
            int m = tid + 256, k = m >> 5, off = (m & 31) * 4;
            cp16(base + (unsigned)(k*COT + off)*4u, g_w1t + (size_t)(c*9 + k)*CC + cob + off);
        }
        cp_commit();
    };
    auto fetch = [&](int c) {
        const float* xp = xb + (size_t)c*HW;
#pragma unroll
        for (int t = 0; t < 3; t++) {
            int i = tid + t*256;
            if (t < 2 || i < NS) {
                pv[t][0] = __ldg(xp + s_ix[0][i]);
                pv[t][1] = __ldg(xp + s_ix[1][i]);
                pv[t][2] = __ldg(xp + s_ix[2][i]);
                pv[t][3] = __ldg(xp + s_ix[3][i]);
            }
        }
    };
    auto store_v = [&](int dbuf) {
#pragma unroll
        for (int t = 0; t < 3; t++) {
            int i = tid + t*256;
            if (t < 2 || i < NS) {
                s_v[dbuf][i] = pv[t][0]*s_bw[0][i] + pv[t][1]*s_bw[1][i]
                             + pv[t][2]*s_bw[2][i] + pv[t][3]*s_bw[3][i];
            }
        }
    };

    int tco = (tid >> 4) * 8;   // 0..120 (co-pairs: 4 u64)
    int tpx = (tid & 15) * 4;   // 0..60

    u64 acc[4][4];
#pragma unroll
    for (int m = 0; m < 4; m++)
#pragma unroll
        for (int j = 0; j < 4; j++) acc[m][j] = 0ull;

    stage_w(0, 0);
    fetch(0);

    for (int c = 0; c < CC; c++) {
        int buf = c & 1;
        cp_wait0();
        store_v(buf);
        __syncthreads();
        if (c + 1 < CC) { stage_w(c + 1, buf ^ 1); fetch(c + 1); }
#pragma unroll
        for (int k = 0; k < 9; k++) {
            const u64* wp = (const u64*)&s_w[buf][k][tco];
            u64 a0 = wp[0], a1 = wp[1], a2 = wp[2], a3 = wp[3];
            float4 b4 = *(const float4*)&s_v[buf][k*PXT + tpx];
            u64 b0 = dup2(b4.x), b1 = dup2(b4.y), b2 = dup2(b4.z), b3 = dup2(b4.w);
            fma2(acc[0][0], a0, b0); fma2(acc[0][1], a0, b1); fma2(acc[0][2], a0, b2); fma2(acc[0][3], a0, b3);
            fma2(acc[1][0], a1, b0); fma2(acc[1][1], a1, b1); fma2(acc[1][2], a1, b2); fma2(acc[1][3], a1, b3);
            fma2(acc[2][0], a2, b0); fma2(acc[2][1], a2, b1); fma2(acc[2][2], a2, b2); fma2(acc[2][3], a2, b3);
            fma2(acc[3][0], a3, b0); fma2(acc[3][1], a3, b1); fma2(acc[3][2], a3, b2); fma2(acc[3][3], a3, b3);
        }
    }

#pragma unroll
    for (int m = 0; m < 4; m++) {
        float lo[4], hi[4];
#pragma unroll
        for (int j = 0; j < 4; j++) unpack2(acc[m][j], lo[j], hi[j]);
        float* o0 = g_t1 + ((size_t)(b*CC + cob + tco + 2*m)) * HW + pb + tpx;
        *(float4*)o0        = make_float4(lo[0], lo[1], lo[2], lo[3]);
        *(float4*)(o0 + HW) = make_float4(hi[0], hi[1], hi[2], hi[3]);
    }
}

// ---------------- BN stats ----------------
__global__ void bn_stats(int which, const float* __restrict__ gamma,
                         const float* __restrict__ beta) {
    int c = blockIdx.x;
    const float* t = (which == 0) ? g_t1 : g_t3;
    float s = 0.f, q = 0.f;
    for (int b = 0; b < BB; b++) {
        const float* p = t + ((size_t)(b*CC + c)) * HW;
        for (int i = threadIdx.x; i < HW; i += 256) {
            float v = p[i];
            s += v; q += v*v;
        }
    }
    __shared__ float rs[8], rq[8];
#pragma unroll
    for (int o = 16; o; o >>= 1) {
        s += __shfl_down_sync(0xffffffffu, s, o);
        q += __shfl_down_sync(0xffffffffu, q, o);
    }
    int wid = threadIdx.x / 32, lid = threadIdx.x % 32;
    if (lid == 0) { rs[wid] = s; rq[wid] = q; }
    __syncthreads();
    if (threadIdx.x == 0) {
        s = rs[0]; q = rq[0];
        for (int i = 1; i < 8; i++) { s += rs[i]; q += rq[i]; }
        float n = (float)(BB*HW);
        float mean = s / n;
        float var  = q / n - mean*mean;
        float scale = gamma[c] * rsqrtf(var + 1e-5f);
        if (which == 0) { g_s1[c] = scale; g_h1[c] = beta[c] - mean*scale; }
        else            { g_s2[c] = scale; g_h2[c] = beta[c] - mean*scale; }
    }
}

// ---------------- conv2: 3x3 pad=1, pipelined, f32x2, fused BN1+ReLU ----------------
__global__ void __launch_bounds__(256, 2) conv2_k() {
    int b   = blockIdx.z;
    int cob = blockIdx.y * COT;
    int pb  = blockIdx.x * PXT;
    int tid = threadIdx.x;

    __shared__ float s_w[2][9][COT];
    __shared__ float s_v[2][NS];
    __shared__ int   s_ix[NS];
    __shared__ float s_vd[NS];

    for (int i = tid; i < NS; i += 256) {
        int k = i / PXT, j = i % PXT;
        int p = pb + j, h = p / WW, w = p % WW;
        int y = h + k/3 - 1, xx = w + k%3 - 1;
        int ok = ((unsigned)y < HH && (unsigned)xx < WW);
        s_ix[i] = ok ? (y*WW + xx) : 0;
        s_vd[i] = ok ? 1.f : 0.f;
    }
    __syncthreads();

    const float* tb = g_t1 + (size_t)b*CC*HW;
    float pv[3];

    auto stage_w = [&](int c, int dbuf) {
        unsigned base = (unsigned)__cvta_generic_to_shared(&s_w[dbuf][0][0]);
        {
            int m = tid, k = m >> 5, off = (m & 31) * 4;
            cp16(base + (unsigned)(k*COT + off)*4u, g_w2t + (size_t)(c*9 + k)*CC + cob + off);
        }
        if (tid < 32) {
            int m = tid + 256, k = m >> 5, off = (m & 31) * 4;
            cp16(base + (unsigned)(k*COT + off)*4u, g_w2t + (size_t)(c*9 + k)*CC + cob + off);
        }
        cp_commit();
    };
    auto fetch = [&](int c) {
        const float* tp = tb + (size_t)c*HW;
#pragma unroll
        for (int t = 0; t < 3; t++) {
            int i = tid + t*256;
            if (t < 2 || i < NS) pv[t] = __ldg(tp + s_ix[i]);
        }
    };
    auto store_v = [&](int c, int dbuf) {
        float sc = g_s1[c], sh = g_h1[c];
#pragma unroll
        for (int t = 0; t < 3; t++) {
            int i = tid + t*256;
            if (t < 2 || i < NS)
                s_v[dbuf][i] = fmaxf(fmaf(pv[t], sc, sh), 0.f) * s_vd[i];
        }
    };

    int tco = (tid >> 4) * 8;
    int tpx = (tid & 15) * 4;

    u64 acc[4][4];
#pragma unroll
    for (int m = 0; m < 4; m++)
#pragma unroll
        for (int j = 0; j < 4; j++) acc[m][j] = 0ull;

    stage_w(0, 0);
    fetch(0);

    for (int c = 0; c < CC; c++) {
        int buf = c & 1;
        cp_wait0();
        store_v(c, buf);
        __syncthreads();
        if (c + 1 < CC) { stage_w(c + 1, buf ^ 1); fetch(c + 1); }
#pragma unroll
        for (int k = 0; k < 9; k++) {
            const u64* wp = (const u64*)&s_w[buf][k][tco];
            u64 a0 = wp[0], a1 = wp[1], a2 = wp[2], a3 = wp[3];
            float4 b4 = *(const float4*)&s_v[buf][k*PXT + tpx];
            u64 b0 = dup2(b4.x), b1 = dup2(b4.y), b2 = dup2(b4.z), b3 = dup2(b4.w);
            fma2(acc[0][0], a0, b0); fma2(acc[0][1], a0, b1); fma2(acc[0][2], a0, b2); fma2(acc[0][3], a0, b3);
            fma2(acc[1][0], a1, b0); fma2(acc[1][1], a1, b1); fma2(acc[1][2], a1, b2); fma2(acc[1][3], a1, b3);
            fma2(acc[2][0], a2, b0); fma2(acc[2][1], a2, b1); fma2(acc[2][2], a2, b2); fma2(acc[2][3], a2, b3);
            fma2(acc[3][0], a3, b0); fma2(acc[3][1], a3, b1); fma2(acc[3][2], a3, b2); fma2(acc[3][3], a3, b3);
        }
    }

#pragma unroll
    for (int m = 0; m < 4; m++) {
        float lo[4], hi[4];
#pragma unroll
        for (int j = 0; j < 4; j++) unpack2(acc[m][j], lo[j], hi[j]);
        float* o0 = g_t3 + ((size_t)(b*CC + cob + tco + 2*m)) * HW + pb + tpx;
        *(float4*)o0        = make_float4(lo[0], lo[1], lo[2], lo[3]);
        *(float4*)(o0 + HW) = make_float4(hi[0], hi[1], hi[2], hi[3]);
    }
}

// ---------------- epilogue: out = relu(bn2(t3) + x), float4 ----------------
__global__ void epilogue(const float* __restrict__ x, float* __restrict__ out) {
    int i4 = blockIdx.x * blockDim.x + threadIdx.x;
    if (i4 < BB*CC*HW/4) {
        int i = i4 * 4;
        int c = (i / HW) % CC;
        float sc = g_s2[c], sh = g_h2[c];
        float4 t  = *(const float4*)&g_t3[i];
        float4 xv = *(const float4*)&x[i];
        float4 o;
        o.x = fmaxf(fmaf(t.x, sc, sh) + xv.x, 0.f);
        o.y = fmaxf(fmaf(t.y, sc, sh) + xv.y, 0.f);
        o.z = fmaxf(fmaf(t.z, sc, sh) + xv.z, 0.f);
        o.w = fmaxf(fmaf(t.w, sc, sh) + xv.w, 0.f);
        *(float4*)&out[i] = o;
    }
}

// ---------------- launch ----------------
extern "C" void kernel_launch(void* const* d_in, const int* in_sizes, int n_in,
                              void* d_out, int out_size) {
    const float* x      = (const float*)d_in[0];
    const float* w_off  = (const float*)d_in[1];
    const float* b_off  = (const float*)d_in[2];
    const float* w1     = (const float*)d_in[3];
    const float* gamma1 = (const float*)d_in[4];
    const float* beta1  = (const float*)d_in[5];
    const float* w2     = (const float*)d_in[6];
    const float* gamma2 = (const float*)d_in[7];
    const float* beta2  = (const float*)d_in[8];
    float* out = (float*)d_out;

    prep_w<<<(CK*CC + 255)/256, 256>>>(w1, w2);
    offset_conv<<<dim3(14, 4, BB), 224>>>(x, w_off);
    deform_conv<<<dim3(49, 2, BB), 256>>>(x, b_off);
    bn_stats<<<CC, 256>>>(0, gamma1, beta1);
    conv2_k<<<dim3(49, 2, BB), 256>>>();
    bn_stats<<<CC, 256>>>(1, gamma2, beta2);
    epilogue<<<(BB*CC*HW/4 + 255)/256, 256>>>(x, out);
}

// round 6
// speedup vs baseline: 1.5781x; 1.0018x over previous
#include <cuda_runtime.h>

#define BB 4
#define CC 256
#define HH 56
#define WW 56
#define HW 3136          // 56*56
#define CK 2304          // C*9
#define COT 128          // co tile
#define PXT 64           // pixel tile (3136 = 49*64)
#define NS  (9*PXT)      // 576 samples per block per channel
#define NTILE (BB*2*49)  // 392 output tiles per GEMM
#define NPB (BB*49)      // partial-stat slots per channel

typedef unsigned long long u64;

// ---------------- packed fp32x2 helpers ----------------
__device__ __forceinline__ u64 dup2(float x) {
    unsigned u = __float_as_uint(x);
    u64 r; asm("mov.b64 %0, {%1, %1};" : "=l"(r) : "r"(u)); return r;
}
__device__ __forceinline__ void fma2(u64& d, u64 a, u64 b) {
    asm("fma.rn.f32x2 %0, %1, %2, %0;" : "+l"(d) : "l"(a), "l"(b));
}
__device__ __forceinline__ void unpack2(u64 v, float& lo, float& hi) {
    unsigned a, b;
    asm("mov.b64 {%0, %1}, %2;" : "=r"(a), "=r"(b) : "l"(v));
    lo = __uint_as_float(a); hi = __uint_as_float(b);
}
// ---------------- cp.async helpers ----------------
__device__ __forceinline__ void cp16(unsigned dst, const void* src) {
    asm volatile("cp.async.ca.shared.global [%0], [%1], 16;" :: "r"(dst), "l"(src));
}
__device__ __forceinline__ void cp_commit() { asm volatile("cp.async.commit_group;"); }
__device__ __forceinline__ void cp_wait0()  { asm volatile("cp.async.wait_group 0;"); }

// ---------------- scratch (static device memory) ----------------
__device__ float g_offp[4][BB*18*HW];  // offset conv partials (C-quarters)
__device__ float g_t1 [BB*CC*HW];      // deform conv output (pre-BN)
__device__ float g_t3 [BB*CC*HW];      // conv2 output (pre-BN)
__device__ float g_w1t[CK*CC];         // w1 transposed: [c*9+k][co]
__device__ float g_w2t[CK*CC];         // w2 transposed
__device__ float g_s1[CC], g_h1[CC];   // bn1 scale/shift
__device__ float g_s2[CC], g_h2[CC];   // bn2 scale/shift
__device__ unsigned g_ctr[2];          // work-steal counters (deform, conv2)
__device__ float g_p1s[NPB*CC], g_p1q[NPB*CC];   // per-tile bn1 partials
__device__ float g_p2s[NPB*CC], g_p2q[NPB*CC];   // per-tile bn2 partials

// ---------------- prep: weight transpose + counter reset ----------------
__global__ void prep_w(const float* __restrict__ w1, const float* __restrict__ w2) {
    int i = blockIdx.x * blockDim.x + threadIdx.x;
    if (i < 2) g_ctr[i] = 0u;
    if (i < CK*CC) {
        int co = i / CK, r = i % CK;
        g_w1t[r*CC + co] = w1[i];
        g_w2t[r*CC + co] = w2[i];
    }
}

// ---------------- offset conv: 3x3 dil=2 pad=2, C-quarter partials, f32x2 ----------------
__global__ void __launch_bounds__(224) offset_conv(const float* __restrict__ x,
                                                   const float* __restrict__ w_off) {
    int b = blockIdx.z, q = blockIdx.y;
    int p = blockIdx.x * 224 + threadIdx.x;
    int h = p / WW, w = p % WW;
    __shared__ float w_sm[9][20];   // [k][co] padded (18 -> 20), 8B-aligned rows
    u64 acc[9];
#pragma unroll
    for (int m = 0; m < 9; m++) acc[m] = 0ull;

    const float* xb = x + ((size_t)(b*CC + q*64)) * HW;
    for (int c = 0; c < 64; c++) {
        __syncthreads();
        if (threadIdx.x < 162) {
            int co = threadIdx.x / 9, kk = threadIdx.x % 9;
            w_sm[kk][co] = w_off[co*CK + (q*64 + c)*9 + kk];
        }
        __syncthreads();
        float sv[9];
        const float* xp = xb + c*HW;
#pragma unroll
        for (int k = 0; k < 9; k++) {
            int yy = h + (k/3)*2 - 2;
            int xx = w + (k%3)*2 - 2;
            sv[k] = ((unsigned)yy < HH && (unsigned)xx < WW) ? xp[yy*WW + xx] : 0.f;
        }
#pragma unroll
        for (int k = 0; k < 9; k++) {
            u64 s2 = dup2(sv[k]);
            const u64* wp = (const u64*)&w_sm[k][0];
#pragma unroll
            for (int m = 0; m < 9; m++) fma2(acc[m], wp[m], s2);
        }
    }
#pragma unroll
    for (int m = 0; m < 9; m++) {
        float lo, hi; unpack2(acc[m], lo, hi);
        g_offp[q][(size_t)(b*18 + 2*m    )*HW + p] = lo;
        g_offp[q][(size_t)(b*18 + 2*m + 1)*HW + p] = hi;
    }
}

// ---------------- deformable conv: persistent work-stealing implicit GEMM, f32x2 ----------------
// 296 blocks, 256 threads, 2/SM. Tiles: t -> coi = t&1, pbi = (t>>1)%49, b = (t>>1)/49.
// Fused deterministic BN1 partial stats into the epilogue.
__global__ void __launch_bounds__(256, 2) deform_conv(const float* __restrict__ x,
                                                      const float* __restrict__ b_off) {
    int tid  = threadIdx.x;
    int lane = tid & 31;

    __shared__ float s_w[2][9][COT];   // double-buffered weights
    __shared__ float s_v[2][NS];       // double-buffered sampled operand
    __shared__ int   s_ix[4][NS];      // 4 clamped corner flat indices
    __shared__ float s_bw[4][NS];      // 4 masked bilinear weights
    __shared__ unsigned s_tile;

    int tco = (tid >> 4) * 8;   // 0..120 (co-pairs: 4 u64)
    int tpx = (tid & 15) * 4;   // 0..60

    for (;;) {
        __syncthreads();
        if (tid == 0) s_tile = atomicAdd(&g_ctr[0], 1u);
        __syncthreads();
        unsigned t = s_tile;
        if (t >= NTILE) return;
        int coi = t & 1;
        int pbi = (t >> 1) % 49;
        int b   = (t >> 1) / 49;
        int cob = coi * COT;
        int pb  = pbi * PXT;

        // ---- meta (once per tile) ----
        for (int i = tid; i < NS; i += 256) {
            int k = i / PXT, j = i % PXT;
            int p = pb + j, h = p / WW, w = p % WW;
            size_t o = (size_t)(b*18 + 2*k)*HW + p;
            float dy = g_offp[0][o] + g_offp[1][o] + g_offp[2][o] + g_offp[3][o] + b_off[2*k];
            o += HW;
            float dx = g_offp[0][o] + g_offp[1][o] + g_offp[2][o] + g_offp[3][o] + b_off[2*k + 1];
            float py = (float)(h + (k/3)*2 - 2) + dy;
            float px = (float)(w + (k%3)*2 - 2) + dx;
            float y0f = floorf(py), x0f = floorf(px);
            float wy = py - y0f, wx = px - x0f;
            int yi = (int)y0f, xi = (int)x0f;
            float vy0 = ((unsigned)yi      < HH) ? 1.f : 0.f;
            float vy1 = ((unsigned)(yi+1)  < HH) ? 1.f : 0.f;
            float vx0 = ((unsigned)xi      < WW) ? 1.f : 0.f;
            float vx1 = ((unsigned)(xi+1)  < WW) ? 1.f : 0.f;
            int cy0 = min(max(yi,   0), HH-1), cy1 = min(max(yi+1, 0), HH-1);
            int cx0 = min(max(xi,   0), WW-1), cx1 = min(max(xi+1, 0), WW-1);
            s_ix[0][i] = cy0*WW + cx0;  s_ix[1][i] = cy0*WW + cx1;
            s_ix[2][i] = cy1*WW + cx0;  s_ix[3][i] = cy1*WW + cx1;
            s_bw[0][i] = (1.f-wy)*(1.f-wx)*vy0*vx0;
            s_bw[1][i] = (1.f-wy)*wx      *vy0*vx1;
            s_bw[2][i] = wy*(1.f-wx)      *vy1*vx0;
            s_bw[3][i] = wy*wx            *vy1*vx1;
        }
        __syncthreads();

        const float* xb = x + (size_t)b*CC*HW;
        float pv[3][4];

        auto stage_w = [&](int c, int dbuf) {
            unsigned base = (unsigned)__cvta_generic_to_shared(&s_w[dbuf][0][0]);
            {
                int m = tid, k = m >> 5, off = (m & 31) * 4;
                cp16(base + (unsigned)(k*COT + off)*4u, g_w1t + (size_t)(c*9 + k)*CC + cob + off);
            }
            if (tid < 32) {
                int m = tid + 256, k = m >> 5, off = (m & 31) * 4;
                cp16(base + (unsigned)(k*COT + off)*4u, g_w1t + (size_t)(c*9 + k)*CC + cob + off);
            }
            cp_commit();
        };
        auto fetch = [&](int c) {
            const float* xp = xb + (size_t)c*HW;
#pragma unroll
            for (int u = 0; u < 3; u++) {
                int i = tid + u*256;
                if (u < 2 || i < NS) {
                    pv[u][0] = __ldg(xp + s_ix[0][i]);
                    pv[u][1] = __ldg(xp + s_ix[1][i]);
                    pv[u][2] = __ldg(xp + s_ix[2][i]);
                    pv[u][3] = __ldg(xp + s_ix[3][i]);
                }
            }
        };
        auto store_v = [&](int dbuf) {
#pragma unroll
            for (int u = 0; u < 3; u++) {
                int i = tid + u*256;
                if (u < 2 || i < NS) {
                    s_v[dbuf][i] = pv[u][0]*s_bw[0][i] + pv[u][1]*s_bw[1][i]
                                 + pv[u][2]*s_bw[2][i] + pv[u][3]*s_bw[3][i];
                }
            }
        };

        u64 acc[4][4];
#pragma unroll
        for (int m = 0; m < 4; m++)
#pragma unroll
            for (int j = 0; j < 4; j++) acc[m][j] = 0ull;

        stage_w(0, 0);
        fetch(0);

        for (int c = 0; c < CC; c++) {
            int buf = c & 1;
            cp_wait0();
            store_v(buf);
            __syncthreads();
            if (c + 1 < CC) { stage_w(c + 1, buf ^ 1); fetch(c + 1); }
#pragma unroll
            for (int k = 0; k < 9; k++) {
                const u64* wp = (const u64*)&s_w[buf][k][tco];
                u64 a0 = wp[0], a1 = wp[1], a2 = wp[2], a3 = wp[3];
                float4 b4 = *(const float4*)&s_v[buf][k*PXT + tpx];
                u64 b0 = dup2(b4.x), b1 = dup2(b4.y), b2 = dup2(b4.z), b3 = dup2(b4.w);
                fma2(acc[0][0], a0, b0); fma2(acc[0][1], a0, b1); fma2(acc[0][2], a0, b2); fma2(acc[0][3], a0, b3);
                fma2(acc[1][0], a1, b0); fma2(acc[1][1], a1, b1); fma2(acc[1][2], a1, b2); fma2(acc[1][3], a1, b3);
                fma2(acc[2][0], a2, b0); fma2(acc[2][1], a2, b1); fma2(acc[2][2], a2, b2); fma2(acc[2][3], a2, b3);
                fma2(acc[3][0], a3, b0); fma2(acc[3][1], a3, b1); fma2(acc[3][2], a3, b2); fma2(acc[3][3], a3, b3);
            }
        }

        // ---- epilogue: store + deterministic BN1 partial stats ----
#pragma unroll
        for (int m = 0; m < 4; m++) {
            float lo[4], hi[4];
#pragma unroll
            for (int j = 0; j < 4; j++) unpack2(acc[m][j], lo[j], hi[j]);
            float* o0 = g_t1 + ((size_t)(b*CC + cob + tco + 2*m)) * HW + pb + tpx;
            *(float4*)o0        = make_float4(lo[0], lo[1], lo[2], lo[3]);
            *(float4*)(o0 + HW) = make_float4(hi[0], hi[1], hi[2], hi[3]);
            float sl = lo[0]+lo[1]+lo[2]+lo[3];
            float ql = lo[0]*lo[0]+lo[1]*lo[1]+lo[2]*lo[2]+lo[3]*lo[3];
            float sh = hi[0]+hi[1]+hi[2]+hi[3];
            float qh = hi[0]*hi[0]+hi[1]*hi[1]+hi[2]*hi[2]+hi[3]*hi[3];
#pragma unroll
            for (int o = 8; o; o >>= 1) {
                sl += __shfl_xor_sync(0xffffffffu, sl, o, 16);
                ql += __shfl_xor_sync(0xffffffffu, ql, o, 16);
                sh += __shfl_xor_sync(0xffffffffu, sh, o, 16);
                qh += __shfl_xor_sync(0xffffffffu, qh, o, 16);
            }
            if ((lane & 15) == 0) {
                int base = (b*49 + pbi)*CC + cob + tco + 2*m;
                g_p1s[base]   = sl;  g_p1q[base]   = ql;
                g_p1s[base+1] = sh;  g_p1q[base+1] = qh;
            }
        }
    }
}

// ---------------- BN finalize: fold per-tile partials -> scale/shift ----------------
__global__ void bn_finalize(int which, const float* __restrict__ gamma,
                            const float* __restrict__ beta) {
    int c = threadIdx.x;   // 256 threads = CC
    const float* ps = (which == 0) ? g_p1s : g_p2s;
    const float* pq = (which == 0) ? g_p1q : g_p2q;
    float s = 0.f, q = 0.f;
    for (int t = 0; t < NPB; t++) { s += ps[t*CC + c]; q += pq[t*CC + c]; }
    float n = (float)(BB*HW);
    float mean = s / n;
    float var  = q / n - mean*mean;
    float scale = gamma[c] * rsqrtf(var + 1e-5f);
    if (which == 0) { g_s1[c] = scale; g_h1[c] = beta[c] - mean*scale; }
    else            { g_s2[c] = scale; g_h2[c] = beta[c] - mean*scale; }
}

// ---------------- conv2: persistent work-stealing, f32x2, fused BN1+ReLU + BN2 stats ----------------
__global__ void __launch_bounds__(256, 2) conv2_k() {
    int tid  = threadIdx.x;
    int lane = tid & 31;

    __shared__ float s_w[2][9][COT];
    __shared__ float s_v[2][NS];
    __shared__ int   s_ix[NS];
    __shared__ float s_vd[NS];
    __shared__ unsigned s_tile;

    int tco = (tid >> 4) * 8;
    int tpx = (tid & 15) * 4;

    for (;;) {
        __syncthreads();
        if (tid == 0) s_tile = atomicAdd(&g_ctr[1], 1u);
        __syncthreads();
        unsigned t = s_tile;
        if (t >= NTILE) return;
        int coi = t & 1;
        int pbi = (t >> 1) % 49;
        int b   = (t >> 1) / 49;
        int cob = coi * COT;
        int pb  = pbi * PXT;

        for (int i = tid; i < NS; i += 256) {
            int k = i / PXT, j = i % PXT;
            int p = pb + j, h = p / WW, w = p % WW;
            int y = h + k/3 - 1, xx = w + k%3 - 1;
            int ok = ((unsigned)y < HH && (unsigned)xx < WW);
            s_ix[i] = ok ? (y*WW + xx) : 0;
            s_vd[i] = ok ? 1.f : 0.f;
        }
        __syncthreads();

        const float* tb = g_t1 + (size_t)b*CC*HW;
        float pv[3];

        auto stage_w = [&](int c, int dbuf) {
            unsigned base = (unsigned)__cvta_generic_to_shared(&s_w[dbuf][0][0]);
            {
                int m = tid, k = m >> 5, off = (m & 31) * 4;
                cp16(base + (unsigned)(k*COT + off)*4u, g_w2t + (size_t)(c*9 + k)*CC + cob + off);
            }
            if (tid < 32) {
                int m = tid + 256, k = m >> 5, off = (m & 31) * 4;
                cp16(base + (unsigned)(k*COT + off)*4u, g_w2t + (size_t)(c*9 + k)*CC + cob + off);
            }
            cp_commit();
        };
        auto fetch = [&](int c) {
            const float* tp = tb + (size_t)c*HW;
#pragma unroll
            for (int u = 0; u < 3; u++) {
                int i = tid + u*256;
                if (u < 2 || i < NS) pv[u] = __ldg(tp + s_ix[i]);
            }
        };
        auto store_v = [&](int c, int dbuf) {
            float sc = g_s1[c], sh = g_h1[c];
#pragma unroll
            for (int u = 0; u < 3; u++) {
                int i = tid + u*256;
                if (u < 2 || i < NS)
                    s_v[dbuf][i] = fmaxf(fmaf(pv[u], sc, sh), 0.f) * s_vd[i];
            }
        };

        u64 acc[4][4];
#pragma unroll
        for (int m = 0; m < 4; m++)
#pragma unroll
            for (int j = 0; j < 4; j++) acc[m][j] = 0ull;

        stage_w(0, 0);
        fetch(0);

        for (int c = 0; c < CC; c++) {
            int buf = c & 1;
            cp_wait0();
            store_v(c, buf);
            __syncthreads();
            if (c + 1 < CC) { stage_w(c + 1, buf ^ 1); fetch(c + 1); }
#pragma unroll
            for (int k = 0; k < 9; k++) {
                const u64* wp = (const u64*)&s_w[buf][k][tco];
                u64 a0 = wp[0], a1 = wp[1], a2 = wp[2], a3 = wp[3];
                float4 b4 = *(const float4*)&s_v[buf][k*PXT + tpx];
                u64 b0 = dup2(b4.x), b1 = dup2(b4.y), b2 = dup2(b4.z), b3 = dup2(b4.w);
                fma2(acc[0][0], a0, b0); fma2(acc[0][1], a0, b1); fma2(acc[0][2], a0, b2); fma2(acc[0][3], a0, b3);
                fma2(acc[1][0], a1, b0); fma2(acc[1][1], a1, b1); fma2(acc[1][2], a1, b2); fma2(acc[1][3], a1, b3);
                fma2(acc[2][0], a2, b0); fma2(acc[2][1], a2, b1); fma2(acc[2][2], a2, b2); fma2(acc[2][3], a2, b3);
                fma2(acc[3][0], a3, b0); fma2(acc[3][1], a3, b1); fma2(acc[3][2], a3, b2); fma2(acc[3][3], a3, b3);
            }
        }

#pragma unroll
        for (int m = 0; m < 4; m++) {
            float lo[4], hi[4];
#pragma unroll
            for (int j = 0; j < 4; j++) unpack2(acc[m][j], lo[j], hi[j]);
            float* o0 = g_t3 + ((size_t)(b*CC + cob + tco + 2*m)) * HW + pb + tpx;
            *(float4*)o0        = make_float4(lo[0], lo[1], lo[2], lo[3]);
            *(float4*)(o0 + HW) = make_float4(hi[0], hi[1], hi[2], hi[3]);
            float sl = lo[0]+lo[1]+lo[2]+lo[3];
            float ql = lo[0]*lo[0]+lo[1]*lo[1]+lo[2]*lo[2]+lo[3]*lo[3];
            float sh = hi[0]+hi[1]+hi[2]+hi[3];
            float qh = hi[0]*hi[0]+hi[1]*hi[1]+hi[2]*hi[2]+hi[3]*hi[3];
#pragma unroll
            for (int o = 8; o; o >>= 1) {
                sl += __shfl_xor_sync(0xffffffffu, sl, o, 16);
                ql += __shfl_xor_sync(0xffffffffu, ql, o, 16);
                sh += __shfl_xor_sync(0xffffffffu, sh, o, 16);
                qh += __shfl_xor_sync(0xffffffffu, qh, o, 16);
            }
            if ((lane & 15) == 0) {
                int base = (b*49 + pbi)*CC + cob + tco + 2*m;
                g_p2s[base]   = sl;  g_p2q[base]   = ql;
                g_p2s[base+1] = sh;  g_p2q[base+1] = qh;
            }
        }
    }
}

// ---------------- epilogue: out = relu(bn2(t3) + x), float4 ----------------
__global__ void epilogue(const float* __restrict__ x, float* __restrict__ out) {
    int i4 = blockIdx.x * blockDim.x + threadIdx.x;
    if (i4 < BB*CC*HW/4) {
        int i = i4 * 4;
        int c = (i / HW) % CC;
        float sc = g_s2[c], sh = g_h2[c];
        float4 t  = *(const float4*)&g_t3[i];
        float4 xv = *(const float4*)&x[i];
        float4 o;
        o.x = fmaxf(fmaf(t.x, sc, sh) + xv.x, 0.f);
        o.y = fmaxf(fmaf(t.y, sc, sh) + xv.y, 0.f);
        o.z = fmaxf(fmaf(t.z, sc, sh) + xv.z, 0.f);
        o.w = fmaxf(fmaf(t.w, sc, sh) + xv.w, 0.f);
        *(float4*)&out[i] = o;
    }
}

// ---------------- launch ----------------
extern "C" void kernel_launch(void* const* d_in, const int* in_sizes, int n_in,
                              void* d_out, int out_size) {
    const float* x      = (const float*)d_in[0];
    const float* w_off  = (const float*)d_in[1];
    const float* b_off  = (const float*)d_in[2];
    const float* w1     = (const float*)d_in[3];
    const float* gamma1 = (const float*)d_in[4];
    const float* beta1  = (const float*)d_in[5];
    const float* w2     = (const float*)d_in[6];
    const float* gamma2 = (const float*)d_in[7];
    const float* beta2  = (const float*)d_in[8];
    float* out = (float*)d_out;

    prep_w<<<(CK*CC + 255)/256, 256>>>(w1, w2);
    offset_conv<<<dim3(14, 4, BB), 224>>>(x, w_off);
    deform_conv<<<296, 256>>>(x, b_off);
    bn_finalize<<<1, 256>>>(0, gamma1, beta1);
    conv2_k<<<296, 256>>>();
    bn_finalize<<<1, 256>>>(1, gamma2, beta2);
    epilogue<<<(BB*CC*HW/4 + 255)/256, 256>>>(x, out);
}

// round 9
// speedup vs baseline: 1.8568x; 1.1766x over previous
#include <cuda_runtime.h>
#include <cuda_bf16.h>
#include <cstdint>

#define BB 4
#define CC 256
#define HH 56
#define WW 56
#define HW 3136          // 56*56
#define CK 2304          // C*9
#define COT 128          // co tile
#define PXT 64           // pixel tile (3136 = 49*64)
#define NS  (9*PXT)      // 576 samples per block per channel
#define NTILE (BB*2*49)  // 392 output tiles per GEMM
#define NPB (BB*49)      // partial-stat slots per channel (196)
#define NSEG 144         // conv2 K-steps: 9 k-pos x 16 channel-chunks of 16

typedef unsigned long long u64;

// ---------------- packed fp32x2 helpers ----------------
__device__ __forceinline__ u64 dup2(float x) {
    unsigned u = __float_as_uint(x);
    u64 r; asm("mov.b64 %0, {%1, %1};" : "=l"(r) : "r"(u)); return r;
}
__device__ __forceinline__ void fma2(u64& d, u64 a, u64 b) {
    asm("fma.rn.f32x2 %0, %1, %2, %0;" : "+l"(d) : "l"(a), "l"(b));
}
__device__ __forceinline__ void unpack2(u64 v, float& lo, float& hi) {
    unsigned a, b;
    asm("mov.b64 {%0, %1}, %2;" : "=r"(a), "=r"(b) : "l"(v));
    lo = __uint_as_float(a); hi = __uint_as_float(b);
}
// ---------------- cp.async helpers ----------------
__device__ __forceinline__ void cp16(unsigned dst, const void* src) {
    asm volatile("cp.async.ca.shared.global [%0], [%1], 16;" :: "r"(dst), "l"(src));
}
__device__ __forceinline__ void cp_commit() { asm volatile("cp.async.commit_group;"); }
__device__ __forceinline__ void cp_wait0()  { asm volatile("cp.async.wait_group 0;"); }

// ---------------- mma.sync / ldmatrix helpers (sm_80-era, sm_103-safe) ----------------
__device__ __forceinline__ unsigned smem_u32(const void* p) {
    unsigned a;
    asm("{ .reg .u64 t; cvta.to.shared.u64 t, %1; cvt.u32.u64 %0, t; }" : "=r"(a) : "l"(p));
    return a;
}
__device__ __forceinline__ void ldsm4(uint32_t* r, unsigned a) {
    asm volatile("ldmatrix.sync.aligned.m8n8.x4.shared.b16 {%0,%1,%2,%3}, [%4];"
                 : "=r"(r[0]), "=r"(r[1]), "=r"(r[2]), "=r"(r[3]) : "r"(a));
}
__device__ __forceinline__ void ldsm4t(uint32_t* r, unsigned a) {
    asm volatile("ldmatrix.sync.aligned.m8n8.x4.trans.shared.b16 {%0,%1,%2,%3}, [%4];"
                 : "=r"(r[0]), "=r"(r[1]), "=r"(r[2]), "=r"(r[3]) : "r"(a));
}
__device__ __forceinline__ void mma_bf(float* d, const uint32_t* a, uint32_t b0, uint32_t b1) {
    asm volatile(
        "mma.sync.aligned.m16n8k16.row.col.f32.bf16.bf16.f32 "
        "{%0,%1,%2,%3}, {%4,%5,%6,%7}, {%8,%9}, {%0,%1,%2,%3};"
        : "+f"(d[0]), "+f"(d[1]), "+f"(d[2]), "+f"(d[3])
        : "r"(a[0]), "r"(a[1]), "r"(a[2]), "r"(a[3]), "r"(b0), "r"(b1));
}
__device__ __forceinline__ uint32_t bf16x2_rn(float hi_src, float lo_src) {
    uint32_t r;
    asm("cvt.rn.bf16x2.f32 %0, %1, %2;" : "=r"(r) : "f"(hi_src), "f"(lo_src));
    return r;
}
#define SWZ(o)  ((o) ^ (((o) >> 3) & 0x70))          // SW128 for 128B rows
#define ASWZ(o) ((o) ^ (((o) & 0x80) >> 3))          // conflict-free for 32B rows

// ---------------- scratch (static device memory) ----------------
__device__ float g_offp[4][BB*18*HW];  // offset conv partials (C-quarters)
__device__ float g_t1 [BB*CC*HW];      // deform conv output (pre-BN)
__device__ float g_t3 [BB*CC*HW];      // conv2 output (pre-BN)
__device__ float g_w1t[CK*CC];         // w1 transposed: [c*9+k][co]
__device__ __align__(16) __nv_bfloat16 g_w2bh[NSEG*CC*16];  // w2 bf16 hi: [seg][co(256)][ci]
__device__ __align__(16) __nv_bfloat16 g_w2bl[NSEG*CC*16];  // w2 bf16 lo
__device__ float g_s1[CC], g_h1[CC];   // bn1 scale/shift
__device__ float g_s2[CC], g_h2[CC];   // bn2 scale/shift
__device__ unsigned g_ctr[2];          // work-steal counters
__device__ float g_p1s[NPB*CC], g_p1q[NPB*CC];   // per-tile bn1 partials
__device__ float g_p2s[NPB*CC], g_p2q[NPB*CC];   // per-tile bn2 partials

// ---------------- prep: w1 transpose, w2 bf16 split, counter reset ----------------
__global__ void prep_w(const float* __restrict__ w1, const float* __restrict__ w2) {
    int i = blockIdx.x * blockDim.x + threadIdx.x;
    if (i < 2) g_ctr[i] = 0u;
    if (i < CK*CC) {
        int co = i / CK, r = i % CK;
        int c = r / 9, k = r % 9;
        g_w1t[r*CC + co] = w1[i];
        float v = w2[i];
        unsigned vb = __float_as_uint(v);
        float hif = __uint_as_float(vb & 0xFFFF0000u);          // truncated bf16 hi
        __nv_bfloat16 hi = __ushort_as_bfloat16((unsigned short)(vb >> 16));
        __nv_bfloat16 lo = __float2bfloat16_rn(v - hif);
        int seg = k*16 + (c >> 4), ci = c & 15;
        g_w2bh[((size_t)seg*CC + co)*16 + ci] = hi;
        g_w2bl[((size_t)seg*CC + co)*16 + ci] = lo;
    }
}

// ---------------- offset conv (unchanged) ----------------
__global__ void __launch_bounds__(224) offset_conv(const float* __restrict__ x,
                                                   const float* __restrict__ w_off) {
    int b = blockIdx.z, q = blockIdx.y;
    int p = blockIdx.x * 224 + threadIdx.x;
    int h = p / WW, w = p % WW;
    __shared__ float w_sm[9][20];
    u64 acc[9];
#pragma unroll
    for (int m = 0; m < 9; m++) acc[m] = 0ull;

    const float* xb = x + ((size_t)(b*CC + q*64)) * HW;
    for (int c = 0; c < 64; c++) {
        __syncthreads();
        if (threadIdx.x < 162) {
            int co = threadIdx.x / 9, kk = threadIdx.x % 9;
            w_sm[kk][co] = w_off[co*CK + (q*64 + c)*9 + kk];
        }
        __syncthreads();
        float sv[9];
        const float* xp = xb + c*HW;
#pragma unroll
        for (int k = 0; k < 9; k++) {
            int yy = h + (k/3)*2 - 2;
            int xx = w + (k%3)*2 - 2;
            sv[k] = ((unsigned)yy < HH && (unsigned)xx < WW) ? xp[yy*WW + xx] : 0.f;
        }
#pragma unroll
        for (int k = 0; k < 9; k++) {
            u64 s2 = dup2(sv[k]);
            const u64* wp = (const u64*)&w_sm[k][0];
#pragma unroll
            for (int m = 0; m < 9; m++) fma2(acc[m], wp[m], s2);
        }
    }
#pragma unroll
    for (int m = 0; m < 9; m++) {
        float lo, hi; unpack2(acc[m], lo, hi);
        g_offp[q][(size_t)(b*18 + 2*m    )*HW + p] = lo;
        g_offp[q][(size_t)(b*18 + 2*m + 1)*HW + p] = hi;
    }
}

// ---------------- deformable conv (unchanged from passing R6) ----------------
__global__ void __launch_bounds__(256, 2) deform_conv(const float* __restrict__ x,
                                                      const float* __restrict__ b_off) {
    int tid  = threadIdx.x;
    int lane = tid & 31;

    __shared__ float s_w[2][9][COT];
    __shared__ float s_v[2][NS];
    __shared__ int   s_ix[4][NS];
    __shared__ float s_bw[4][NS];
    __shared__ unsigned s_tile;

    int tco = (tid >> 4) * 8;
    int tpx = (tid & 15) * 4;

    for (;;) {
        __syncthreads();
        if (tid == 0) s_tile = atomicAdd(&g_ctr[0], 1u);
        __syncthreads();
        unsigned t = s_tile;
        if (t >= NTILE) return;
        int coi = t & 1;
        int pbi = (t >> 1) % 49;
        int b   = (t >> 1) / 49;
        int cob = coi * COT;
        int pb  = pbi * PXT;

        for (int i = tid; i < NS; i += 256) {
            int k = i / PXT, j = i % PXT;
            int p = pb + j, h = p / WW, w = p % WW;
            size_t o = (size_t)(b*18 + 2*k)*HW + p;
            float dy = g_offp[0][o] + g_offp[1][o] + g_offp[2][o] + g_offp[3][o] + b_off[2*k];
            o += HW;
            float dx = g_offp[0][o] + g_offp[1][o] + g_offp[2][o] + g_offp[3][o] + b_off[2*k + 1];
            float py = (float)(h + (k/3)*2 - 2) + dy;
            float px = (float)(w + (k%3)*2 - 2) + dx;
            float y0f = floorf(py), x0f = floorf(px);
            float wy = py - y0f, wx = px - x0f;
            int yi = (int)y0f, xi = (int)x0f;
            float vy0 = ((unsigned)yi      < HH) ? 1.f : 0.f;
            float vy1 = ((unsigned)(yi+1)  < HH) ? 1.f : 0.f;
            float vx0 = ((unsigned)xi      < WW) ? 1.f : 0.f;
            float vx1 = ((unsigned)(xi+1)  < WW) ? 1.f : 0.f;
            int cy0 = min(max(yi,   0), HH-1), cy1 = min(max(yi+1, 0), HH-1);
            int cx0 = min(max(xi,   0), WW-1), cx1 = min(max(xi+1, 0), WW-1);
            s_ix[0][i] = cy0*WW + cx0;  s_ix[1][i] = cy0*WW + cx1;
            s_ix[2][i] = cy1*WW + cx0;  s_ix[3][i] = cy1*WW + cx1;
            s_bw[0][i] = (1.f-wy)*(1.f-wx)*vy0*vx0;
            s_bw[1][i] = (1.f-wy)*wx      *vy0*vx1;
            s_bw[2][i] = wy*(1.f-wx)      *vy1*vx0;
            s_bw[3][i] = wy*wx            *vy1*vx1;
        }
        __syncthreads();

        const float* xb = x + (size_t)b*CC*HW;
        float pv[3][4];

        auto stage_w = [&](int c, int dbuf) {
            unsigned base = (unsigned)__cvta_generic_to_shared(&s_w[dbuf][0][0]);
            {
                int m = tid, k = m >> 5, off = (m & 31) * 4;
                cp16(base + (unsigned)(k*COT + off)*4u, g_w1t + (size_t)(c*9 + k)*CC + cob + off);
            }
            if (tid < 32) {
                int m = tid + 256, k = m >> 5, off = (m & 31) * 4;
                cp16(base + (unsigned)(k*COT + off)*4u, g_w1t + (size_t)(c*9 + k)*CC + cob + off);
            }
            cp_commit();
        };
        auto fetch = [&](int c) {
            const float* xp = xb + (size_t)c*HW;
#pragma unroll
            for (int u = 0; u < 3; u++) {
                int i = tid + u*256;
                if (u < 2 || i < NS) {
                    pv[u][0] = __ldg(xp + s_ix[0][i]);
                    pv[u][1] = __ldg(xp + s_ix[1][i]);
                    pv[u][2] = __ldg(xp + s_ix[2][i]);
                    pv[u][3] = __ldg(xp + s_ix[3][i]);
                }
            }
        };
        auto store_v = [&](int dbuf) {
#pragma unroll
            for (int u = 0; u < 3; u++) {
                int i = tid + u*256;
                if (u < 2 || i < NS) {
                    s_v[dbuf][i] = pv[u][0]*s_bw[0][i] + pv[u][1]*s_bw[1][i]
                                 + pv[u][2]*s_bw[2][i] + pv[u][3]*s_bw[3][i];
                }
            }
        };

        u64 acc[4][4];
#pragma unroll
        for (int m = 0; m < 4; m++)
#pragma unroll
            for (int j = 0; j < 4; j++) acc[m][j] = 0ull;

        stage_w(0, 0);
        fetch(0);

        for (int c = 0; c < CC; c++) {
            int buf = c & 1;
            cp_wait0();
            store_v(buf);
            __syncthreads();
            if (c + 1 < CC) { stage_w(c + 1, buf ^ 1); fetch(c + 1); }
#pragma unroll
            for (int k = 0; k < 9; k++) {
                const u64* wp = (const u64*)&s_w[buf][k][tco];
                u64 a0 = wp[0], a1 = wp[1], a2 = wp[2], a3 = wp[3];
                float4 b4 = *(const float4*)&s_v[buf][k*PXT + tpx];
                u64 b0 = dup2(b4.x), b1 = dup2(b4.y), b2 = dup2(b4.z), b3 = dup2(b4.w);
                fma2(acc[0][0], a0, b0); fma2(acc[0][1], a0, b1); fma2(acc[0][2], a0, b2); fma2(acc[0][3], a0, b3);
                fma2(acc[1][0], a1, b0); fma2(acc[1][1], a1, b1); fma2(acc[1][2], a1, b2); fma2(acc[1][3], a1, b3);
                fma2(acc[2][0], a2, b0); fma2(acc[2][1], a2, b1); fma2(acc[2][2], a2, b2); fma2(acc[2][3], a2, b3);
                fma2(acc[3][0], a3, b0); fma2(acc[3][1], a3, b1); fma2(acc[3][2], a3, b2); fma2(acc[3][3], a3, b3);
            }
        }

#pragma unroll
        for (int m = 0; m < 4; m++) {
            float lo[4], hi[4];
#pragma unroll
            for (int j = 0; j < 4; j++) unpack2(acc[m][j], lo[j], hi[j]);
            float* o0 = g_t1 + ((size_t)(b*CC + cob + tco + 2*m)) * HW + pb + tpx;
            *(float4*)o0        = make_float4(lo[0], lo[1], lo[2], lo[3]);
            *(float4*)(o0 + HW) = make_float4(hi[0], hi[1], hi[2], hi[3]);
            float sl = lo[0]+lo[1]+lo[2]+lo[3];
            float ql = lo[0]*lo[0]+lo[1]*lo[1]+lo[2]*lo[2]+lo[3]*lo[3];
            float sh = hi[0]+hi[1]+hi[2]+hi[3];
            float qh = hi[0]*hi[0]+hi[1]*hi[1]+hi[2]*hi[2]+hi[3]*hi[3];
#pragma unroll
            for (int o = 8; o; o >>= 1) {
                sl += __shfl_xor_sync(0xffffffffu, sl, o, 16);
                ql += __shfl_xor_sync(0xffffffffu, ql, o, 16);
                sh += __shfl_xor_sync(0xffffffffu, sh, o, 16);
                qh += __shfl_xor_sync(0xffffffffu, qh, o, 16);
            }
            if ((lane & 15) == 0) {
                int base = (b*49 + pbi)*CC + cob + tco + 2*m;
                g_p1s[base]   = sl;  g_p1q[base]   = ql;
                g_p1s[base+1] = sh;  g_p1q[base+1] = qh;
            }
        }
    }
}

// ---------------- BN finalize: 256 blocks x 64 threads, deterministic ----------------
__global__ void bn_finalize(int which, const float* __restrict__ gamma,
                            const float* __restrict__ beta) {
    int c = blockIdx.x, t = threadIdx.x;
    const float* ps = (which == 0) ? g_p1s : g_p2s;
    const float* pq = (which == 0) ? g_p1q : g_p2q;
    float s = 0.f, q = 0.f;
    for (int i = t; i < NPB; i += 64) { s += ps[i*CC + c]; q += pq[i*CC + c]; }
    __shared__ float as[2], aq[2];
#pragma unroll
    for (int o = 16; o; o >>= 1) {
        s += __shfl_down_sync(0xffffffffu, s, o);
        q += __shfl_down_sync(0xffffffffu, q, o);
    }
    if ((t & 31) == 0) { as[t >> 5] = s; aq[t >> 5] = q; }
    __syncthreads();
    if (t == 0) {
        s = as[0] + as[1]; q = aq[0] + aq[1];
        float n = (float)(BB*HW);
        float mean = s / n;
        float var  = q / n - mean*mean;
        float scale = gamma[c] * rsqrtf(var + 1e-5f);
        if (which == 0) { g_s1[c] = scale; g_h1[c] = beta[c] - mean*scale; }
        else            { g_s2[c] = scale; g_h2[c] = beta[c] - mean*scale; }
    }
}

// ---------------- conv2: mma.sync bf16 2-split implicit GEMM ----------------
// 392 CTAs, 256 threads (8 warps). Tile 128co x 64px. K = 144 segs of 16 channels.
// Warp w owns co rows [w*16, w*16+16), full 64 px. Fused BN1+ReLU (B build)
// and BN2 partial stats (epilogue).
struct C2S {
    float s1[CC], h1[CC];
    int   ix[NS];
    float vd[NS];
    __align__(16) unsigned char Abuf[2][2][4096];   // [stage][hi/lo]: 128co x 16ci bf16, ASWZ
    __align__(16) unsigned char Bbuf[2][2][2048];   // [stage][hi/lo]: 16c x 64px bf16, SWZ
};

__global__ void __launch_bounds__(256, 2) conv2_mma() {
    __shared__ C2S s;
    const int tid = threadIdx.x, wid = tid >> 5, lid = tid & 31;
    const int t  = blockIdx.x;
    const int pt = t >> 1, coi = t & 1;
    const int b  = pt / 49, pbi = pt % 49;
    const int cob = coi * COT, pb = pbi * PXT;

    // meta
    s.s1[tid] = g_s1[tid];
    s.h1[tid] = g_h1[tid];
    for (int i = tid; i < NS; i += 256) {
        int k = i / PXT, j = i % PXT;
        int p = pb + j, h = p / WW, w = p % WW;
        int y = h + k/3 - 1, xx = w + k%3 - 1;
        int ok = ((unsigned)y < HH && (unsigned)xx < WW);
        s.ix[i] = ok ? (y*WW + xx) : 0;
        s.vd[i] = ok ? 1.f : 0.f;
    }
    __syncthreads();

    const unsigned uA = smem_u32(&s.Abuf[0][0][0]);
    const unsigned uB = smem_u32(&s.Bbuf[0][0][0]);

    // per-thread constant offsets
    const int cl  = tid >> 4;            // 0..15  (B-build channel-local)
    const int pxg = (tid & 15) * 4;      // 0..60  (B-build 4 px)
    const unsigned bswz = SWZ((unsigned)(cl*128 + pxg*2));
    const int aco = tid >> 1, ahalf = tid & 1;          // A cp.async: co row + 16B half
    const unsigned adst = ASWZ((unsigned)(aco*32 + ahalf*16));
    const unsigned aoff = ASWZ((unsigned)((wid*16 + (lid & 15))*32 + (lid >> 4)*16)); // ldmatrix A
    unsigned boff[4];
#pragma unroll
    for (int j = 0; j < 4; j++)
        boff[j] = SWZ((unsigned)((lid & 15)*128 + (j*2 + (lid >> 4))*16));           // ldmatrix B

    float acc[8][4];
#pragma unroll
    for (int j = 0; j < 8; j++)
#pragma unroll
        for (int m = 0; m < 4; m++) acc[j][m] = 0.f;

    const float* tb = g_t1 + (size_t)b*CC*HW;
    float pv[4];
    float sc_r = 0.f, sh_r = 0.f;
    int ibr = 0;

    auto stage_A = [&](int seg, int st) {
        size_t so = ((size_t)seg*CC + cob + aco)*16 + ahalf*8;
        cp16(uA + (unsigned)(st*8192)        + adst, g_w2bh + so);
        cp16(uA + (unsigned)(st*8192 + 4096) + adst, g_w2bl + so);
        cp_commit();
    };
    auto fetch = [&](int seg) {
        int k = seg >> 4, cb = seg & 15;
        int c = cb*16 + cl;
        ibr = k*PXT + pxg;
        sc_r = s.s1[c]; sh_r = s.h1[c];
        const float* tp = tb + (size_t)c*HW;
#pragma unroll
        for (int j = 0; j < 4; j++) pv[j] = __ldg(tp + s.ix[ibr + j]);
    };
    auto store_B = [&](int st) {
        float w0 = fmaxf(fmaf(pv[0], sc_r, sh_r), 0.f) * s.vd[ibr];
        float w1 = fmaxf(fmaf(pv[1], sc_r, sh_r), 0.f) * s.vd[ibr + 1];
        float w2 = fmaxf(fmaf(pv[2], sc_r, sh_r), 0.f) * s.vd[ibr + 2];
        float w3 = fmaxf(fmaf(pv[3], sc_r, sh_r), 0.f) * s.vd[ibr + 3];
        unsigned b0 = __float_as_uint(w0), b1 = __float_as_uint(w1);
        unsigned b2 = __float_as_uint(w2), b3 = __float_as_uint(w3);
        unsigned hA = __byte_perm(b0, b1, 0x7632);
        unsigned hB = __byte_perm(b2, b3, 0x7632);
        float l0 = w0 - __uint_as_float(b0 & 0xFFFF0000u);
        float l1 = w1 - __uint_as_float(b1 & 0xFFFF0000u);
        float l2 = w2 - __uint_as_float(b2 & 0xFFFF0000u);
        float l3 = w3 - __uint_as_float(b3 & 0xFFFF0000u);
        unsigned lA = bf16x2_rn(l1, l0);
        unsigned lB = bf16x2_rn(l3, l2);
        *(uint2*)&s.Bbuf[st][0][bswz] = make_uint2(hA, hB);
        *(uint2*)&s.Bbuf[st][1][bswz] = make_uint2(lA, lB);
    };

    stage_A(0, 0);
    fetch(0);

    for (int seg = 0; seg < NSEG; seg++) {
        int st = seg & 1;
        cp_wait0();
        store_B(st);
        __syncthreads();
        if (seg + 1 < NSEG) { stage_A(seg + 1, st ^ 1); fetch(seg + 1); }

        uint32_t ah[4], al[4];
        ldsm4(ah, uA + (unsigned)(st*8192)        + aoff);
        ldsm4(al, uA + (unsigned)(st*8192 + 4096) + aoff);
#pragma unroll
        for (int j = 0; j < 4; j++) {
            uint32_t bh[4], bl[4];
            ldsm4t(bh, uB + (unsigned)(st*4096)        + boff[j]);
            ldsm4t(bl, uB + (unsigned)(st*4096 + 2048) + boff[j]);
            mma_bf(acc[2*j],     ah, bh[0], bh[1]);
            mma_bf(acc[2*j],     ah, bl[0], bl[1]);
            mma_bf(acc[2*j],     al, bh[0], bh[1]);
            mma_bf(acc[2*j + 1], ah, bh[2], bh[3]);
            mma_bf(acc[2*j + 1], ah, bl[2], bl[3]);
            mma_bf(acc[2*j + 1], al, bh[2], bh[3]);
        }
    }

    // epilogue: fragment rows -> g_t3 + deterministic BN2 partials
    {
        int co0 = cob + wid*16 + (lid >> 2);
        int co1 = co0 + 8;
        int pxo = (lid & 3) * 2;
        float* r0 = g_t3 + ((size_t)(b*CC + co0))*HW + pb + pxo;
        float* r1 = g_t3 + ((size_t)(b*CC + co1))*HW + pb + pxo;
        float s0 = 0.f, q0 = 0.f, s1v = 0.f, q1v = 0.f;
#pragma unroll
        for (int j = 0; j < 8; j++) {
            float v0 = acc[j][0], v1 = acc[j][1], v2 = acc[j][2], v3 = acc[j][3];
            r0[j*8]     = v0;  r0[j*8 + 1] = v1;
            r1[j*8]     = v2;  r1[j*8 + 1] = v3;
            s0 += v0 + v1;  q0 += v0*v0 + v1*v1;
            s1v += v2 + v3; q1v += v2*v2 + v3*v3;
        }
#pragma unroll
        for (int o = 1; o <= 2; o <<= 1) {
            s0  += __shfl_xor_sync(0xffffffffu, s0,  o, 4);
            q0  += __shfl_xor_sync(0xffffffffu, q0,  o, 4);
            s1v += __shfl_xor_sync(0xffffffffu, s1v, o, 4);
            q1v += __shfl_xor_sync(0xffffffffu, q1v, o, 4);
        }
        if ((lid & 3) == 0) {
            g_p2s[pt*CC + co0] = s0;   g_p2q[pt*CC + co0] = q0;
            g_p2s[pt*CC + co1] = s1v;  g_p2q[pt*CC + co1] = q1v;
        }
    }
}

// ---------------- epilogue: out = relu(bn2(t3) + x), float4 ----------------
__global__ void epilogue(const float* __restrict__ x, float* __restrict__ out) {
    int i4 = blockIdx.x * blockDim.x + threadIdx.x;
    if (i4 < BB*CC*HW/4) {
        int i = i4 * 4;
        int c = (i / HW) % CC;
        float sc = g_s2[c], sh = g_h2[c];
        float4 t  = *(const float4*)&g_t3[i];
        float4 xv = *(const float4*)&x[i];
        float4 o;
        o.x = fmaxf(fmaf(t.x, sc, sh) + xv.x, 0.f);
        o.y = fmaxf(fmaf(t.y, sc, sh) + xv.y, 0.f);
        o.z = fmaxf(fmaf(t.z, sc, sh) + xv.z, 0.f);
        o.w = fmaxf(fmaf(t.w, sc, sh) + xv.w, 0.f);
        *(float4*)&out[i] = o;
    }
}

// ---------------- launch ----------------
extern "C" void kernel_launch(void* const* d_in, const int* in_sizes, int n_in,
                              void* d_out, int out_size) {
    const float* x      = (const float*)d_in[0];
    const float* w_off  = (const float*)d_in[1];
    const float* b_off  = (const float*)d_in[2];
    const float* w1     = (const float*)d_in[3];
    const float* gamma1 = (const float*)d_in[4];
    const float* beta1  = (const float*)d_in[5];
    const float* w2     = (const float*)d_in[6];
    const float* gamma2 = (const float*)d_in[7];
    const float* beta2  = (const float*)d_in[8];
    float* out = (float*)d_out;

    prep_w<<<(CK*CC + 255)/256, 256>>>(w1, w2);
    offset_conv<<<dim3(14, 4, BB), 224>>>(x, w_off);
    deform_conv<<<296, 256>>>(x, b_off);
    bn_finalize<<<CC, 64>>>(0, gamma1, beta1);
    conv2_mma<<<NTILE, 256>>>();
    bn_finalize<<<CC, 64>>>(1, gamma2, beta2);
    epilogue<<<(BB*CC*HW/4 + 255)/256, 256>>>(x, out);
}

// round 10
// speedup vs baseline: 1.9065x; 1.0268x over previous
#include <cuda_runtime.h>
#include <cuda_bf16.h>
#include <cstdint>

#define BB 4
#define CC 256
#define HH 56
#define WW 56
#define HW 3136          // 56*56
#define CK 2304          // C*9
#define COT 128          // co tile
#define PXT 64           // pixel tile (3136 = 49*64)
#define NS  (9*PXT)      // 576 samples per block per channel
#define NTILE (BB*2*49)  // 392 output tiles per GEMM
#define NPB (BB*49)      // partial-stat slots per channel (196)
#define NSEG 144         // K-steps: 9 k-pos x 16 channel-chunks of 16

typedef unsigned long long u64;

// ---------------- packed fp32x2 helpers ----------------
__device__ __forceinline__ u64 dup2(float x) {
    unsigned u = __float_as_uint(x);
    u64 r; asm("mov.b64 %0, {%1, %1};" : "=l"(r) : "r"(u)); return r;
}
__device__ __forceinline__ void fma2(u64& d, u64 a, u64 b) {
    asm("fma.rn.f32x2 %0, %1, %2, %0;" : "+l"(d) : "l"(a), "l"(b));
}
__device__ __forceinline__ void unpack2(u64 v, float& lo, float& hi) {
    unsigned a, b;
    asm("mov.b64 {%0, %1}, %2;" : "=r"(a), "=r"(b) : "l"(v));
    lo = __uint_as_float(a); hi = __uint_as_float(b);
}
// ---------------- cp.async helpers ----------------
__device__ __forceinline__ void cp16(unsigned dst, const void* src) {
    asm volatile("cp.async.ca.shared.global [%0], [%1], 16;" :: "r"(dst), "l"(src));
}
__device__ __forceinline__ void cp_commit() { asm volatile("cp.async.commit_group;"); }
__device__ __forceinline__ void cp_wait0()  { asm volatile("cp.async.wait_group 0;"); }

// ---------------- mma.sync / ldmatrix helpers ----------------
__device__ __forceinline__ unsigned smem_u32(const void* p) {
    unsigned a;
    asm("{ .reg .u64 t; cvta.to.shared.u64 t, %1; cvt.u32.u64 %0, t; }" : "=r"(a) : "l"(p));
    return a;
}
__device__ __forceinline__ void ldsm4(uint32_t* r, unsigned a) {
    asm volatile("ldmatrix.sync.aligned.m8n8.x4.shared.b16 {%0,%1,%2,%3}, [%4];"
                 : "=r"(r[0]), "=r"(r[1]), "=r"(r[2]), "=r"(r[3]) : "r"(a));
}
__device__ __forceinline__ void ldsm4t(uint32_t* r, unsigned a) {
    asm volatile("ldmatrix.sync.aligned.m8n8.x4.trans.shared.b16 {%0,%1,%2,%3}, [%4];"
                 : "=r"(r[0]), "=r"(r[1]), "=r"(r[2]), "=r"(r[3]) : "r"(a));
}
__device__ __forceinline__ void mma_bf(float* d, const uint32_t* a, uint32_t b0, uint32_t b1) {
    asm volatile(
        "mma.sync.aligned.m16n8k16.row.col.f32.bf16.bf16.f32 "
        "{%0,%1,%2,%3}, {%4,%5,%6,%7}, {%8,%9}, {%0,%1,%2,%3};"
        : "+f"(d[0]), "+f"(d[1]), "+f"(d[2]), "+f"(d[3])
        : "r"(a[0]), "r"(a[1]), "r"(a[2]), "r"(a[3]), "r"(b0), "r"(b1));
}
__device__ __forceinline__ uint32_t bf16x2_rn(float hi_src, float lo_src) {
    uint32_t r;
    asm("cvt.rn.bf16x2.f32 %0, %1, %2;" : "=r"(r) : "f"(hi_src), "f"(lo_src));
    return r;
}
#define SWZ(o)  ((o) ^ (((o) >> 3) & 0x70))          // SW128 for 128B rows
#define ASWZ(o) ((o) ^ (((o) & 0x80) >> 3))          // conflict-free for 32B rows

// ---------------- scratch (static device memory) ----------------
__device__ float g_offp[4][BB*18*HW];  // offset conv partials (C-quarters)
__device__ float g_t1 [BB*CC*HW];      // deform conv output (pre-BN)
__device__ float g_t3 [BB*CC*HW];      // conv2 output (pre-BN)
__device__ __align__(16) __nv_bfloat16 g_w1bh[NSEG*CC*16];  // w1 bf16 hi: [seg][co][ci]
__device__ __align__(16) __nv_bfloat16 g_w1bl[NSEG*CC*16];  // w1 bf16 lo
__device__ __align__(16) __nv_bfloat16 g_w2bh[NSEG*CC*16];  // w2 bf16 hi
__device__ __align__(16) __nv_bfloat16 g_w2bl[NSEG*CC*16];  // w2 bf16 lo
__device__ float g_s1[CC], g_h1[CC];   // bn1 scale/shift
__device__ float g_s2[CC], g_h2[CC];   // bn2 scale/shift
__device__ float g_p1s[NPB*CC], g_p1q[NPB*CC];   // per-tile bn1 partials
__device__ float g_p2s[NPB*CC], g_p2q[NPB*CC];   // per-tile bn2 partials

// ---------------- prep: bf16 split of w1 and w2 into [seg][co][ci] ----------------
__global__ void prep_w(const float* __restrict__ w1, const float* __restrict__ w2) {
    int i = blockIdx.x * blockDim.x + threadIdx.x;
    if (i < CK*CC) {
        int co = i / CK, r = i % CK;
        int c = r / 9, k = r % 9;
        int seg = k*16 + (c >> 4), ci = c & 15;
        size_t o = ((size_t)seg*CC + co)*16 + ci;

        float v = w1[i];
        unsigned vb = __float_as_uint(v);
        g_w1bh[o] = __ushort_as_bfloat16((unsigned short)(vb >> 16));
        g_w1bl[o] = __float2bfloat16_rn(v - __uint_as_float(vb & 0xFFFF0000u));

        v = w2[i];
        vb = __float_as_uint(v);
        g_w2bh[o] = __ushort_as_bfloat16((unsigned short)(vb >> 16));
        g_w2bl[o] = __float2bfloat16_rn(v - __uint_as_float(vb & 0xFFFF0000u));
    }
}

// ---------------- offset conv (unchanged) ----------------
__global__ void __launch_bounds__(224) offset_conv(const float* __restrict__ x,
                                                   const float* __restrict__ w_off) {
    int b = blockIdx.z, q = blockIdx.y;
    int p = blockIdx.x * 224 + threadIdx.x;
    int h = p / WW, w = p % WW;
    __shared__ float w_sm[9][20];
    u64 acc[9];
#pragma unroll
    for (int m = 0; m < 9; m++) acc[m] = 0ull;

    const float* xb = x + ((size_t)(b*CC + q*64)) * HW;
    for (int c = 0; c < 64; c++) {
        __syncthreads();
        if (threadIdx.x < 162) {
            int co = threadIdx.x / 9, kk = threadIdx.x % 9;
            w_sm[kk][co] = w_off[co*CK + (q*64 + c)*9 + kk];
        }
        __syncthreads();
        float sv[9];
        const float* xp = xb + c*HW;
#pragma unroll
        for (int k = 0; k < 9; k++) {
            int yy = h + (k/3)*2 - 2;
            int xx = w + (k%3)*2 - 2;
            sv[k] = ((unsigned)yy < HH && (unsigned)xx < WW) ? xp[yy*WW + xx] : 0.f;
        }
#pragma unroll
        for (int k = 0; k < 9; k++) {
            u64 s2 = dup2(sv[k]);
            const u64* wp = (const u64*)&w_sm[k][0];
#pragma unroll
            for (int m = 0; m < 9; m++) fma2(acc[m], wp[m], s2);
        }
    }
#pragma unroll
    for (int m = 0; m < 9; m++) {
        float lo, hi; unpack2(acc[m], lo, hi);
        g_offp[q][(size_t)(b*18 + 2*m    )*HW + p] = lo;
        g_offp[q][(size_t)(b*18 + 2*m + 1)*HW + p] = hi;
    }
}

// ---------------- shared layouts for the two mma GEMMs ----------------
struct DS {   // deform
    int   ix[4][NS];
    float bw[4][NS];
    __align__(16) unsigned char Abuf[2][2][4096];
    __align__(16) unsigned char Bbuf[2][2][2048];
};
struct C2S {  // conv2
    float s1[CC], h1[CC];
    int   ix[NS];
    float vd[NS];
    __align__(16) unsigned char Abuf[2][2][4096];
    __align__(16) unsigned char Bbuf[2][2][2048];
};

// ---------------- deformable conv: mma.sync bf16 2-split implicit GEMM ----------------
// 392 CTAs, 256 threads. Tile 128co x 64px, K = 144 segs of (k-pos, 16 channels).
// B operand built by bilinear sampling; BN1 partial stats fused in epilogue.
__global__ void __launch_bounds__(256, 2) deform_mma(const float* __restrict__ x,
                                                     const float* __restrict__ b_off) {
    __shared__ DS s;
    const int tid = threadIdx.x, wid = tid >> 5, lid = tid & 31;
    const int t  = blockIdx.x;
    const int pt = t >> 1, coi = t & 1;
    const int b  = pt / 49, pbi = pt % 49;
    const int cob = coi * COT, pb = pbi * PXT;

    // meta: bilinear corner indices + masked weights, once per tile
    for (int i = tid; i < NS; i += 256) {
        int k = i / PXT, j = i % PXT;
        int p = pb + j, h = p / WW, w = p % WW;
        size_t o = (size_t)(b*18 + 2*k)*HW + p;
        float dy = g_offp[0][o] + g_offp[1][o] + g_offp[2][o] + g_offp[3][o] + b_off[2*k];
        o += HW;
        float dx = g_offp[0][o] + g_offp[1][o] + g_offp[2][o] + g_offp[3][o] + b_off[2*k + 1];
        float py = (float)(h + (k/3)*2 - 2) + dy;
        float px = (float)(w + (k%3)*2 - 2) + dx;
        float y0f = floorf(py), x0f = floorf(px);
        float wy = py - y0f, wx = px - x0f;
        int yi = (int)y0f, xi = (int)x0f;
        float vy0 = ((unsigned)yi      < HH) ? 1.f : 0.f;
        float vy1 = ((unsigned)(yi+1)  < HH) ? 1.f : 0.f;
        float vx0 = ((unsigned)xi      < WW) ? 1.f : 0.f;
        float vx1 = ((unsigned)(xi+1)  < WW) ? 1.f : 0.f;
        int cy0 = min(max(yi,   0), HH-1), cy1 = min(max(yi+1, 0), HH-1);
        int cx0 = min(max(xi,   0), WW-1), cx1 = min(max(xi+1, 0), WW-1);
        s.ix[0][i] = cy0*WW + cx0;  s.ix[1][i] = cy0*WW + cx1;
        s.ix[2][i] = cy1*WW + cx0;  s.ix[3][i] = cy1*WW + cx1;
        s.bw[0][i] = (1.f-wy)*(1.f-wx)*vy0*vx0;
        s.bw[1][i] = (1.f-wy)*wx      *vy0*vx1;
        s.bw[2][i] = wy*(1.f-wx)      *vy1*vx0;
        s.bw[3][i] = wy*wx            *vy1*vx1;
    }
    __syncthreads();

    const unsigned uA = smem_u32(&s.Abuf[0][0][0]);
    const unsigned uB = smem_u32(&s.Bbuf[0][0][0]);

    const int cl  = tid >> 4;            // channel-local 0..15 (B build)
    const int pxg = (tid & 15) * 4;      // 4 px group
    const unsigned bswz = SWZ((unsigned)(cl*128 + pxg*2));
    const int aco = tid >> 1, ahalf = tid & 1;
    const unsigned adst = ASWZ((unsigned)(aco*32 + ahalf*16));
    const unsigned aoff = ASWZ((unsigned)((wid*16 + (lid & 15))*32 + (lid >> 4)*16));
    unsigned boff[4];
#pragma unroll
    for (int j = 0; j < 4; j++)
        boff[j] = SWZ((unsigned)((lid & 15)*128 + (j*2 + (lid >> 4))*16));

    float acc[8][4];
#pragma unroll
    for (int j = 0; j < 8; j++)
#pragma unroll
        for (int m = 0; m < 4; m++) acc[j][m] = 0.f;

    const float* xb = x + (size_t)b*CC*HW;
    float pv[4][4];
    int ibr = 0;

    auto stage_A = [&](int seg, int st) {
        size_t so = ((size_t)seg*CC + cob + aco)*16 + ahalf*8;
        cp16(uA + (unsigned)(st*8192)        + adst, g_w1bh + so);
        cp16(uA + (unsigned)(st*8192 + 4096) + adst, g_w1bl + so);
        cp_commit();
    };
    auto fetch = [&](int seg) {
        int k = seg >> 4, cb = seg & 15;
        int c = cb*16 + cl;
        ibr = k*PXT + pxg;
        const float* xp = xb + (size_t)c*HW;
#pragma unroll
        for (int j = 0; j < 4; j++) {
            int i = ibr + j;
            pv[j][0] = __ldg(xp + s.ix[0][i]);
            pv[j][1] = __ldg(xp + s.ix[1][i]);
            pv[j][2] = __ldg(xp + s.ix[2][i]);
            pv[j][3] = __ldg(xp + s.ix[3][i]);
        }
    };
    auto store_B = [&](int st) {
        float wv[4];
#pragma unroll
        for (int j = 0; j < 4; j++) {
            int i = ibr + j;
            wv[j] = pv[j][0]*s.bw[0][i] + pv[j][1]*s.bw[1][i]
                  + pv[j][2]*s.bw[2][i] + pv[j][3]*s.bw[3][i];
        }
        unsigned b0 = __float_as_uint(wv[0]), b1 = __float_as_uint(wv[1]);
        unsigned b2 = __float_as_uint(wv[2]), b3 = __float_as_uint(wv[3]);
        unsigned hA = __byte_perm(b0, b1, 0x7632);
        unsigned hB = __byte_perm(b2, b3, 0x7632);
        float l0 = wv[0] - __uint_as_float(b0 & 0xFFFF0000u);
        float l1 = wv[1] - __uint_as_float(b1 & 0xFFFF0000u);
        float l2 = wv[2] - __uint_as_float(b2 & 0xFFFF0000u);
        float l3 = wv[3] - __uint_as_float(b3 & 0xFFFF0000u);
        unsigned lA = bf16x2_rn(l1, l0);
        unsigned lB = bf16x2_rn(l3, l2);
        *(uint2*)&s.Bbuf[st][0][bswz] = make_uint2(hA, hB);
        *(uint2*)&s.Bbuf[st][1][bswz] = make_uint2(lA, lB);
    };

    stage_A(0, 0);
    fetch(0);

    for (int seg = 0; seg < NSEG; seg++) {
        int st = seg & 1;
        cp_wait0();
        store_B(st);
        __syncthreads();
        if (seg + 1 < NSEG) { stage_A(seg + 1, st ^ 1); fetch(seg + 1); }

        uint32_t ah[4], al[4];
        ldsm4(ah, uA + (unsigned)(st*8192)        + aoff);
        ldsm4(al, uA + (unsigned)(st*8192 + 4096) + aoff);
#pragma unroll
        for (int j = 0; j < 4; j++) {
            uint32_t bh[4], bl[4];
            ldsm4t(bh, uB + (unsigned)(st*4096)        + boff[j]);
            ldsm4t(bl, uB + (unsigned)(st*4096 + 2048) + boff[j]);
            mma_bf(acc[2*j],     ah, bh[0], bh[1]);
            mma_bf(acc[2*j],     ah, bl[0], bl[1]);
            mma_bf(acc[2*j],     al, bh[0], bh[1]);
            mma_bf(acc[2*j + 1], ah, bh[2], bh[3]);
            mma_bf(acc[2*j + 1], ah, bl[2], bl[3]);
            mma_bf(acc[2*j + 1], al, bh[2], bh[3]);
        }
    }

    // epilogue: fragment rows -> g_t1 + deterministic BN1 partials
    {
        int co0 = cob + wid*16 + (lid >> 2);
        int co1 = co0 + 8;
        int pxo = (lid & 3) * 2;
        float* r0 = g_t1 + ((size_t)(b*CC + co0))*HW + pb + pxo;
        float* r1 = g_t1 + ((size_t)(b*CC + co1))*HW + pb + pxo;
        float s0 = 0.f, q0 = 0.f, s1v = 0.f, q1v = 0.f;
#pragma unroll
        for (int j = 0; j < 8; j++) {
            float v0 = acc[j][0], v1 = acc[j][1], v2 = acc[j][2], v3 = acc[j][3];
            r0[j*8]     = v0;  r0[j*8 + 1] = v1;
            r1[j*8]     = v2;  r1[j*8 + 1] = v3;
            s0 += v0 + v1;  q0 += v0*v0 + v1*v1;
            s1v += v2 + v3; q1v += v2*v2 + v3*v3;
        }
#pragma unroll
        for (int o = 1; o <= 2; o <<= 1) {
            s0  += __shfl_xor_sync(0xffffffffu, s0,  o, 4);
            q0  += __shfl_xor_sync(0xffffffffu, q0,  o, 4);
            s1v += __shfl_xor_sync(0xffffffffu, s1v, o, 4);
            q1v += __shfl_xor_sync(0xffffffffu, q1v, o, 4);
        }
        if ((lid & 3) == 0) {
            g_p1s[pt*CC + co0] = s0;   g_p1q[pt*CC + co0] = q0;
            g_p1s[pt*CC + co1] = s1v;  g_p1q[pt*CC + co1] = q1v;
        }
    }
}

// ---------------- BN finalize: 256 blocks x 64 threads, deterministic ----------------
__global__ void bn_finalize(int which, const float* __restrict__ gamma,
                            const float* __restrict__ beta) {
    int c = blockIdx.x, t = threadIdx.x;
    const float* ps = (which == 0) ? g_p1s : g_p2s;
    const float* pq = (which == 0) ? g_p1q : g_p2q;
    float s = 0.f, q = 0.f;
    for (int i = t; i < NPB; i += 64) { s += ps[i*CC + c]; q += pq[i*CC + c]; }
    __shared__ float as[2], aq[2];
#pragma unroll
    for (int o = 16; o; o >>= 1) {
        s += __shfl_down_sync(0xffffffffu, s, o);
        q += __shfl_down_sync(0xffffffffu, q, o);
    }
    if ((t & 31) == 0) { as[t >> 5] = s; aq[t >> 5] = q; }
    __syncthreads();
    if (t == 0) {
        s = as[0] + as[1]; q = aq[0] + aq[1];
        float n = (float)(BB*HW);
        float mean = s / n;
        float var  = q / n - mean*mean;
        float scale = gamma[c] * rsqrtf(var + 1e-5f);
        if (which == 0) { g_s1[c] = scale; g_h1[c] = beta[c] - mean*scale; }
        else            { g_s2[c] = scale; g_h2[c] = beta[c] - mean*scale; }
    }
}

// ---------------- conv2: mma.sync bf16 2-split implicit GEMM (passing R9) ----------------
__global__ void __launch_bounds__(256, 2) conv2_mma() {
    __shared__ C2S s;
    const int tid = threadIdx.x, wid = tid >> 5, lid = tid & 31;
    const int t  = blockIdx.x;
    const int pt = t >> 1, coi = t & 1;
    const int b  = pt / 49, pbi = pt % 49;
    const int cob = coi * COT, pb = pbi * PXT;

    s.s1[tid] = g_s1[tid];
    s.h1[tid] = g_h1[tid];
    for (int i = tid; i < NS; i += 256) {
        int k = i / PXT, j = i % PXT;
        int p = pb + j, h = p / WW, w = p % WW;
        int y = h + k/3 - 1, xx = w + k%3 - 1;
        int ok = ((unsigned)y < HH && (unsigned)xx < WW);
        s.ix[i] = ok ? (y*WW + xx) : 0;
        s.vd[i] = ok ? 1.f : 0.f;
    }
    __syncthreads();

    const unsigned uA = smem_u32(&s.Abuf[0][0][0]);
    const unsigned uB = smem_u32(&s.Bbuf[0][0][0]);

    const int cl  = tid >> 4;
    const int pxg = (tid & 15) * 4;
    const unsigned bswz = SWZ((unsigned)(cl*128 + pxg*2));
    const int aco = tid >> 1, ahalf = tid & 1;
    const unsigned adst = ASWZ((unsigned)(aco*32 + ahalf*16));
    const unsigned aoff = ASWZ((unsigned)((wid*16 + (lid & 15))*32 + (lid >> 4)*16));
    unsigned boff[4];
#pragma unroll
    for (int j = 0; j < 4; j++)
        boff[j] = SWZ((unsigned)((lid & 15)*128 + (j*2 + (lid >> 4))*16));

    float acc[8][4];
#pragma unroll
    for (int j = 0; j < 8; j++)
#pragma unroll
        for (int m = 0; m < 4; m++) acc[j][m] = 0.f;

    const float* tb = g_t1 + (size_t)b*CC*HW;
    float pv[4];
    float sc_r = 0.f, sh_r = 0.f;
    int ibr = 0;

    auto stage_A = [&](int seg, int st) {
        size_t so = ((size_t)seg*CC + cob + aco)*16 + ahalf*8;
        cp16(uA + (unsigned)(st*8192)        + adst, g_w2bh + so);
        cp16(uA + (unsigned)(st*8192 + 4096) + adst, g_w2bl + so);
        cp_commit();
    };
    auto fetch = [&](int seg) {
        int k = seg >> 4, cb = seg & 15;
        int c = cb*16 + cl;
        ibr = k*PXT + pxg;
        sc_r = s.s1[c]; sh_r = s.h1[c];
        const float* tp = tb + (size_t)c*HW;
#pragma unroll
        for (int j = 0; j < 4; j++) pv[j] = __ldg(tp + s.ix[ibr + j]);
    };
    auto store_B = [&](int st) {
        float w0 = fmaxf(fmaf(pv[0], sc_r, sh_r), 0.f) * s.vd[ibr];
        float w1 = fmaxf(fmaf(pv[1], sc_r, sh_r), 0.f) * s.vd[ibr + 1];
        float w2 = fmaxf(fmaf(pv[2], sc_r, sh_r), 0.f) * s.vd[ibr + 2];
        float w3 = fmaxf(fmaf(pv[3], sc_r, sh_r), 0.f) * s.vd[ibr + 3];
        unsigned b0 = __float_as_uint(w0), b1 = __float_as_uint(w1);
        unsigned b2 = __float_as_uint(w2), b3 = __float_as_uint(w3);
        unsigned hA = __byte_perm(b0, b1, 0x7632);
        unsigned hB = __byte_perm(b2, b3, 0x7632);
        float l0 = w0 - __uint_as_float(b0 & 0xFFFF0000u);
        float l1 = w1 - __uint_as_float(b1 & 0xFFFF0000u);
        float l2 = w2 - __uint_as_float(b2 & 0xFFFF0000u);
        float l3 = w3 - __uint_as_float(b3 & 0xFFFF0000u);
        unsigned lA = bf16x2_rn(l1, l0);
        unsigned lB = bf16x2_rn(l3, l2);
        *(uint2*)&s.Bbuf[st][0][bswz] = make_uint2(hA, hB);
        *(uint2*)&s.Bbuf[st][1][bswz] = make_uint2(lA, lB);
    };

    stage_A(0, 0);
    fetch(0);

    for (int seg = 0; seg < NSEG; seg++) {
        int st = seg & 1;
        cp_wait0();
        store_B(st);
        __syncthreads();
        if (seg + 1 < NSEG) { stage_A(seg + 1, st ^ 1); fetch(seg + 1); }

        uint32_t ah[4], al[4];
        ldsm4(ah, uA + (unsigned)(st*8192)        + aoff);
        ldsm4(al, uA + (unsigned)(st*8192 + 4096) + aoff);
#pragma unroll
        for (int j = 0; j < 4; j++) {
            uint32_t bh[4], bl[4];
            ldsm4t(bh, uB + (unsigned)(st*4096)        + boff[j]);
            ldsm4t(bl, uB + (unsigned)(st*4096 + 2048) + boff[j]);
            mma_bf(acc[2*j],     ah, bh[0], bh[1]);
            mma_bf(acc[2*j],     ah, bl[0], bl[1]);
            mma_bf(acc[2*j],     al, bh[0], bh[1]);
            mma_bf(acc[2*j + 1], ah, bh[2], bh[3]);
            mma_bf(acc[2*j + 1], ah, bl[2], bl[3]);
            mma_bf(acc[2*j + 1], al, bh[2], bh[3]);
        }
    }

    {
        int co0 = cob + wid*16 + (lid >> 2);
        int co1 = co0 + 8;
        int pxo = (lid & 3) * 2;
        float* r0 = g_t3 + ((size_t)(b*CC + co0))*HW + pb + pxo;
        float* r1 = g_t3 + ((size_t)(b*CC + co1))*HW + pb + pxo;
        float s0 = 0.f, q0 = 0.f, s1v = 0.f, q1v = 0.f;
#pragma unroll
        for (int j = 0; j < 8; j++) {
            float v0 = acc[j][0], v1 = acc[j][1], v2 = acc[j][2], v3 = acc[j][3];
            r0[j*8]     = v0;  r0[j*8 + 1] = v1;
            r1[j*8]     = v2;  r1[j*8 + 1] = v3;
            s0 += v0 + v1;  q0 += v0*v0 + v1*v1;
            s1v += v2 + v3; q1v += v2*v2 + v3*v3;
        }
#pragma unroll
        for (int o = 1; o <= 2; o <<= 1) {
            s0  += __shfl_xor_sync(0xffffffffu, s0,  o, 4);
            q0  += __shfl_xor_sync(0xffffffffu, q0,  o, 4);
            s1v += __shfl_xor_sync(0xffffffffu, s1v, o, 4);
            q1v += __shfl_xor_sync(0xffffffffu, q1v, o, 4);
        }
        if ((lid & 3) == 0) {
            g_p2s[pt*CC + co0] = s0;   g_p2q[pt*CC + co0] = q0;
            g_p2s[pt*CC + co1] = s1v;  g_p2q[pt*CC + co1] = q1v;
        }
    }
}

// ---------------- epilogue: out = relu(bn2(t3) + x), float4 ----------------
__global__ void epilogue(const float* __restrict__ x, float* __restrict__ out) {
    int i4 = blockIdx.x * blockDim.x + threadIdx.x;
    if (i4 < BB*CC*HW/4) {
        int i = i4 * 4;
        int c = (i / HW) % CC;
        float sc = g_s2[c], sh = g_h2[c];
        float4 t  = *(const float4*)&g_t3[i];
        float4 xv = *(const float4*)&x[i];
        float4 o;
        o.x = fmaxf(fmaf(t.x, sc, sh) + xv.x, 0.f);
        o.y = fmaxf(fmaf(t.y, sc, sh) + xv.y, 0.f);
        o.z = fmaxf(fmaf(t.z, sc, sh) + xv.z, 0.f);
        o.w = fmaxf(fmaf(t.w, sc, sh) + xv.w, 0.f);
        *(float4*)&out[i] = o;
    }
}

// ---------------- launch ----------------
extern "C" void kernel_launch(void* const* d_in, const int* in_sizes, int n_in,
                              void* d_out, int out_size) {
    const float* x      = (const float*)d_in[0];
    const float* w_off  = (const float*)d_in[1];
    const float* b_off  = (const float*)d_in[2];
    const float* w1     = (const float*)d_in[3];
    const float* gamma1 = (const float*)d_in[4];
    const float* beta1  = (const float*)d_in[5];
    const float* w2     = (const float*)d_in[6];
    const float* gamma2 = (const float*)d_in[7];
    const float* beta2  = (const float*)d_in[8];
    float* out = (float*)d_out;

    prep_w<<<(CK*CC + 255)/256, 256>>>(w1, w2);
    offset_conv<<<dim3(14, 4, BB), 224>>>(x, w_off);
    deform_mma<<<NTILE, 256>>>(x, b_off);
    bn_finalize<<<CC, 64>>>(0, gamma1, beta1);
    conv2_mma<<<NTILE, 256>>>();
    bn_finalize<<<CC, 64>>>(1, gamma2, beta2);
    epilogue<<<(BB*CC*HW/4 + 255)/256, 256>>>(x, out);
}